// round 13
// baseline (speedup 1.0000x reference)
#include <cuda_runtime.h>
#include <cuda_bf16.h>
#include <cstdint>

// ---------------- scratch (device globals; no allocation allowed) ----------------
__device__ unsigned g_s1[1024 * 36 * 32 * 32]; // conv1 out, packed bf16x2(hi,lo)
__device__ unsigned g_s2[1024 * 36 * 16 * 16]; // conv2 out, packed bf16x2(hi,lo)
__device__ float    g_s3[1024 * 36 * 8 * 8];   // conv3 out (fp32, feeds FC)
__device__ float    g_p1[1024 * 12 * 32 * 32]; // private conv out
__device__ float    g_x24[1024 * 24];          // concat [h | p]
__device__ float    g_Wf[9 * 5 * 3 * 32 * 4];  // hidden conv frag weights, ord0 (69 KB)
__device__ float    g_Wc1[9 * 3 * 32 * 4];     // conv1 frag weights, ord0 (13.8 KB)
__device__ float    g_Wp[9 * 1 * 32 * 4];      // private conv frag weights, ord0 (4.6 KB)

// ---------------- packing helpers ----------------
__device__ __forceinline__ unsigned pack_hilo(float v) {
    __nv_bfloat16 h = __float2bfloat16_rn(v);
    float hf = __bfloat162float(h);
    __nv_bfloat16 l = __float2bfloat16_rn(v - hf);
    return (((unsigned)__bfloat16_as_ushort(l)) << 16) | (unsigned)__bfloat16_as_ushort(h);
}
__device__ __forceinline__ unsigned rot16(unsigned w) {   // swap 16-bit halves
    return (w << 16) | (w >> 16);
}

__device__ __forceinline__ void mma_bf16(float* d, const unsigned* a, unsigned b0, unsigned b1) {
    asm volatile(
        "mma.sync.aligned.m16n8k16.row.col.f32.bf16.bf16.f32 "
        "{%0,%1,%2,%3}, {%4,%5,%6,%7}, {%8,%9}, {%0,%1,%2,%3};"
        : "+f"(d[0]), "+f"(d[1]), "+f"(d[2]), "+f"(d[3])
        : "r"(a[0]), "r"(a[1]), "r"(a[2]), "r"(a[3]), "r"(b0), "r"(b1));
}

// ---------------- weight prep (hidden convs): ord0 only ----------------
__global__ void wprep_kernel(const float* __restrict__ W, float* __restrict__ Wf)
{
    int idx = blockIdx.x * blockDim.x + threadIdx.x;
    if (idx >= 9 * 5 * 3 * 32) return;
    int lane = idx & 31;
    int q    = (idx >> 5) % 3;
    int kt   = (idx / 96) % 5;
    int tap  = idx / 480;
    int km = lane & 3, n = lane >> 2;
    int ci0 = kt * 8 + km, ci1 = ci0 + 4;
    int oc0 = q * 16 + n,  oc1 = oc0 + 8;
    auto pk = [&](int ci, int oc) -> float {
        float w = 0.f;
        if (ci < 36 && oc < 36) w = W[((size_t)oc * 36 + ci) * 9 + tap];
        return __uint_as_float(pack_hilo(w));
    };
    float4 f;
    f.x = pk(ci0, oc0); f.y = pk(ci1, oc0);
    f.z = pk(ci0, oc1); f.w = pk(ci1, oc1);
    reinterpret_cast<float4*>(Wf)[idx] = f;
}

// ---------------- weight prep (3-ch convs): k = ci padded 3->8, per tap, ord0 --------
// Layout: W3[tap(9)][q(NQ)][lane(32)] float4.
template <int OC, int NQ, bool USE_DOM>
__global__ void wprep3_kernel(const float* __restrict__ Wbase,
                              const int* __restrict__ dom_ptr,
                              float* __restrict__ Wf)
{
    int idx = blockIdx.x * blockDim.x + threadIdx.x;
    if (idx >= 9 * NQ * 32) return;
    int lane = idx & 31;
    int q    = (idx >> 5) % NQ;
    int tap  = idx / (32 * NQ);
    int km = lane & 3, n = lane >> 2;
    int ci0 = km, ci1 = km + 4;
    int oc0 = q * 16 + n, oc1 = oc0 + 8;
    int dom = USE_DOM ? dom_ptr[0] : 0;
    const float* W = Wbase + (size_t)dom * OC * 27;
    auto pk = [&](int ci, int oc) -> float {
        float w = 0.f;
        if (ci < 3 && oc < OC) w = W[((size_t)oc * 3 + ci) * 9 + tap];
        return __uint_as_float(pack_hilo(w));
    };
    float4 f;
    f.x = pk(ci0, oc0); f.y = pk(ci1, oc0);
    f.z = pk(ci0, oc1); f.w = pk(ci1, oc1);
    reinterpret_cast<float4*>(Wf)[idx] = f;
}

// ---------------- 3-channel conv via bfconv structure (tap loop, IC pad 3->8) --------
// S=64, 16 strips of 4 rows, 8 warps. Stage ONLY 3 real planes (packed inline) + zeros.
// Same validated A-fragment addressing: PHP = 6*76 = 456 ≡ 8 (mod 32).
template <int OC, int NQ, int NTILES, bool LEAKY, bool USE_DOM, bool OUTPACK>
__global__ void __launch_bounds__(256)
bf3conv_kernel(const float* __restrict__ x, const float* __restrict__ Wf,
               const float* __restrict__ Bbase, const int* __restrict__ dom_ptr,
               void* __restrict__ outv)
{
    constexpr int S = 64, SR = 4, PH = SR + 2, P = 76, PHP = PH * P;   // 456
    static_assert(PHP % 32 == 8, "bank layout");
    constexpr int Sp = S / 2;
    extern __shared__ unsigned sx[];   // 8 * PHP words (14.6 KB)

    const int strip = blockIdx.x;
    const int b     = blockIdx.y;
    const int tid   = threadIdx.x;
    const int w     = tid >> 5;
    const int lane  = tid & 31;

    for (int i = tid; i < 8 * PHP; i += 256) sx[i] = 0u;
    __syncthreads();

    // stage 3 real channel planes with halo, packing inline (<=1152 packs per block)
    const int r0  = strip * SR;
    const int gr0 = (r0 - 1 < 0) ? 0 : r0 - 1;
    const int gr1 = (r0 + SR + 1 > S) ? S : r0 + SR + 1;
    const int nrow = gr1 - gr0;
    const float* xb = x + (size_t)b * 3 * S * S;
    for (int i = tid; i < 3 * nrow * S; i += 256) {
        int ci = i / (nrow * S);
        int rr = (i / S) % nrow;
        int c  = i % S;
        int gr = gr0 + rr;
        sx[ci * PHP + (gr - r0 + 1) * P + (c + 1)] = pack_hilo(xb[ci * S * S + gr * S + c]);
    }
    __syncthreads();

    // warp tile: 2 pixel rows x 16 cols (RPAIRS=2, COLT=4)
    const int rp  = w >> 2;
    const int c0  = (w & 3) * 16;
    const int lr0 = 2 * rp;
    const int la  = lane & 3;
    const int lg  = lane >> 2;

    float C[NTILES][2][4];
    #pragma unroll
    for (int n = 0; n < NTILES; n++)
        #pragma unroll
        for (int t = 0; t < 2; t++)
            #pragma unroll
            for (int j = 0; j < 4; j++) C[n][t][j] = 0.f;

    const int aoff0 = la * PHP + lr0 * P + c0 + lg;
    const float4* Wf4 = reinterpret_cast<const float4*>(Wf);

    #pragma unroll
    for (int tap = 0; tap < 9; tap++) {
        const int dy = tap / 3, dx = tap % 3;
        const int abase = aoff0 + dy * P + dx;

        unsigned A[2][4];
        #pragma unroll
        for (int t = 0; t < 2; t++) {
            const unsigned* ap = sx + abase + t * P;
            A[t][0] = ap[0];
            A[t][1] = ap[8];
            A[t][2] = ap[4 * PHP];
            A[t][3] = ap[4 * PHP + 8];
        }
        float4 qa[NQ];
        #pragma unroll
        for (int q = 0; q < NQ; q++)
            qa[q] = __ldg(Wf4 + tap * (NQ * 32) + q * 32 + lane);   // L1-hot (<=13.8 KB)

        #pragma unroll
        for (int n = 0; n < NTILES; n++) {
            int q = n >> 1;
            unsigned b0 = (n & 1) ? __float_as_uint(qa[q].z) : __float_as_uint(qa[q].x);
            unsigned b1 = (n & 1) ? __float_as_uint(qa[q].w) : __float_as_uint(qa[q].y);
            unsigned r0w = rot16(b0), r1w = rot16(b1);
            #pragma unroll
            for (int t = 0; t < 2; t++) {
                mma_bf16(C[n][t], A[t], b0, b1);
                mma_bf16(C[n][t], A[t], r0w, r1w);
            }
        }
    }

    // fused 2x2 maxpool + bias + activation (validated mapping)
    const int dom = USE_DOM ? dom_ptr[0] : 0;
    const float* Bv = Bbase + dom * OC;
    const int pr = strip * 2 + rp;
    #pragma unroll
    for (int n = 0; n < NTILES; n++) {
        float m0 = fmaxf(C[n][0][0], C[n][1][0]);
        float m1 = fmaxf(C[n][0][1], C[n][1][1]);
        float m2 = fmaxf(C[n][0][2], C[n][1][2]);
        float m3 = fmaxf(C[n][0][3], C[n][1][3]);
        float p0 = fmaxf(m0, __shfl_xor_sync(0xffffffffu, m0, 4));
        float p1 = fmaxf(m1, __shfl_xor_sync(0xffffffffu, m1, 4));
        float p2 = fmaxf(m2, __shfl_xor_sync(0xffffffffu, m2, 4));
        float p3 = fmaxf(m3, __shfl_xor_sync(0xffffffffu, m3, 4));
        if ((lane & 4) == 0) {
            int oc0 = n * 8 + (lane & 3) * 2;
            if (oc0 + 1 < OC) {
                int pcb = c0 / 2 + ((lane >> 3) & 3);
                float b0 = __ldg(Bv + oc0);
                float b1 = __ldg(Bv + oc0 + 1);
                float v00 = p0 + b0, v01 = p1 + b1, v10 = p2 + b0, v11 = p3 + b1;
                if (LEAKY) {
                    v00 = v00 > 0.f ? v00 : 0.001f * v00;
                    v01 = v01 > 0.f ? v01 : 0.001f * v01;
                    v10 = v10 > 0.f ? v10 : 0.001f * v10;
                    v11 = v11 > 0.f ? v11 : 0.001f * v11;
                } else {
                    v00 = fmaxf(v00, 0.f); v01 = fmaxf(v01, 0.f);
                    v10 = fmaxf(v10, 0.f); v11 = fmaxf(v11, 0.f);
                }
                size_t o0 = (((size_t)b * OC + oc0) * Sp + pr) * Sp;
                size_t o1 = o0 + (size_t)Sp * Sp;
                if (OUTPACK) {
                    unsigned* out = (unsigned*)outv;
                    out[o0 + pcb]     = pack_hilo(v00);
                    out[o1 + pcb]     = pack_hilo(v01);
                    out[o0 + pcb + 4] = pack_hilo(v10);
                    out[o1 + pcb + 4] = pack_hilo(v11);
                } else {
                    float* out = (float*)outv;
                    out[o0 + pcb]     = v00;
                    out[o1 + pcb]     = v01;
                    out[o0 + pcb + 4] = v10;
                    out[o1 + pcb + 4] = v11;
                }
            }
        }
    }
}

// ---------------- bf16-split implicit-GEMM conv3x3 + relu + maxpool2 (hidden) --------
// R11: double-buffered per-tap B in SMEM, zero-LDG mainloop.
template <int S, int STRIPS, int P, int NWARPS, bool OUTPACK>
__global__ void __launch_bounds__(NWARPS * 32)
bfconv_kernel(const unsigned* __restrict__ x, const float* __restrict__ Wf,
              const float* __restrict__ Bv, void* __restrict__ outv)
{
    constexpr int NT  = NWARPS * 32;
    constexpr int SR  = S / STRIPS;
    constexpr int PH  = SR + 2;
    constexpr int PHP = PH * P;
    static_assert(PHP % 32 == 8, "bank layout");
    constexpr int RPAIRS = SR / 2;
    constexpr int COLT   = S / 16;
    static_assert(RPAIRS * COLT == NWARPS, "warp count");
    constexpr int Sp = S / 2;
    constexpr int WTAP = 5 * 3 * 32;

    extern __shared__ unsigned sx[];
    float4* sB = reinterpret_cast<float4*>(sx + 40 * PHP);   // [2][WTAP]

    const int strip = blockIdx.x;
    const int b     = blockIdx.y;
    const int tid   = threadIdx.x;
    const int w     = tid >> 5;
    const int lane  = tid & 31;

    for (int i = tid; i < 40 * PHP; i += NT) sx[i] = 0u;
    __syncthreads();

    const int r0  = strip * SR;
    const int gr0 = (r0 - 1 < 0) ? 0 : r0 - 1;
    const int gr1 = (r0 + SR + 1 > S) ? S : r0 + SR + 1;
    const int nrow = gr1 - gr0;
    const unsigned* xb = x + (size_t)b * 36 * S * S;
    for (int i = tid; i < 36 * nrow * S; i += NT) {
        int ci = i / (nrow * S);
        int rr = (i / S) % nrow;
        int c  = i % S;
        int gr = gr0 + rr;
        sx[ci * PHP + (gr - r0 + 1) * P + (c + 1)] = xb[ci * S * S + gr * S + c];
    }
    const float4* Wf4 = reinterpret_cast<const float4*>(Wf);
    for (int i = tid; i < WTAP; i += NT) sB[i] = __ldg(Wf4 + i);
    __syncthreads();

    const int rp  = w / COLT;
    const int c0  = (w % COLT) * 16;
    const int lr0 = 2 * rp;
    const int la  = lane & 3;
    const int lg  = lane >> 2;

    float C[5][2][4];
    #pragma unroll
    for (int n = 0; n < 5; n++)
        #pragma unroll
        for (int t = 0; t < 2; t++)
            #pragma unroll
            for (int j = 0; j < 4; j++) C[n][t][j] = 0.f;

    const int aoff0 = la * PHP + lr0 * P + c0 + lg;

    for (int tap = 0; tap < 9; tap++) {
        const int p = tap & 1;
        if (tap + 1 < 9) {
            const float4* src = Wf4 + (tap + 1) * WTAP;
            for (int i = tid; i < WTAP; i += NT) sB[(p ^ 1) * WTAP + i] = __ldg(src + i);
        }

        const int dy = tap / 3, dx = tap % 3;
        const int abase = aoff0 + dy * P + dx;
        const float4* bt = sB + p * WTAP;

        #pragma unroll
        for (int kt = 0; kt < 5; kt++) {
            unsigned A[2][4];
            #pragma unroll
            for (int t = 0; t < 2; t++) {
                const unsigned* ap = sx + abase + t * P + kt * 8 * PHP;
                A[t][0] = ap[0];
                A[t][1] = ap[8];
                A[t][2] = ap[4 * PHP];
                A[t][3] = ap[4 * PHP + 8];
            }
            float4 q0 = bt[kt * 96 + 0 * 32 + lane];
            float4 q1 = bt[kt * 96 + 1 * 32 + lane];
            float4 q2 = bt[kt * 96 + 2 * 32 + lane];

            unsigned Ba[5][2] = {
                {__float_as_uint(q0.x), __float_as_uint(q0.y)},
                {__float_as_uint(q0.z), __float_as_uint(q0.w)},
                {__float_as_uint(q1.x), __float_as_uint(q1.y)},
                {__float_as_uint(q1.z), __float_as_uint(q1.w)},
                {__float_as_uint(q2.x), __float_as_uint(q2.y)} };

            #pragma unroll
            for (int n = 0; n < 5; n++) {
                unsigned b0 = Ba[n][0], b1 = Ba[n][1];
                unsigned r0w = rot16(b0), r1w = rot16(b1);
                #pragma unroll
                for (int t = 0; t < 2; t++) {
                    mma_bf16(C[n][t], A[t], b0, b1);
                    mma_bf16(C[n][t], A[t], r0w, r1w);
                }
            }
        }
        __syncthreads();
    }

    const int pr = strip * RPAIRS + rp;
    #pragma unroll
    for (int n = 0; n < 5; n++) {
        float m0 = fmaxf(C[n][0][0], C[n][1][0]);
        float m1 = fmaxf(C[n][0][1], C[n][1][1]);
        float m2 = fmaxf(C[n][0][2], C[n][1][2]);
        float m3 = fmaxf(C[n][0][3], C[n][1][3]);
        float p0 = fmaxf(m0, __shfl_xor_sync(0xffffffffu, m0, 4));
        float p1 = fmaxf(m1, __shfl_xor_sync(0xffffffffu, m1, 4));
        float p2 = fmaxf(m2, __shfl_xor_sync(0xffffffffu, m2, 4));
        float p3 = fmaxf(m3, __shfl_xor_sync(0xffffffffu, m3, 4));
        if ((lane & 4) == 0) {
            int oc0 = n * 8 + (lane & 3) * 2;
            if (oc0 < 36) {
                int pcb = c0 / 2 + ((lane >> 3) & 3);
                float b0 = __ldg(Bv + oc0);
                float b1 = __ldg(Bv + oc0 + 1);
                float v00 = fmaxf(p0 + b0, 0.f);
                float v01 = fmaxf(p1 + b1, 0.f);
                float v10 = fmaxf(p2 + b0, 0.f);
                float v11 = fmaxf(p3 + b1, 0.f);
                size_t o0 = (((size_t)b * 36 + oc0) * Sp + pr) * Sp;
                size_t o1 = o0 + (size_t)Sp * Sp;
                if (OUTPACK) {
                    unsigned* out = (unsigned*)outv;
                    out[o0 + pcb]     = pack_hilo(v00);
                    out[o1 + pcb]     = pack_hilo(v01);
                    out[o0 + pcb + 4] = pack_hilo(v10);
                    out[o1 + pcb + 4] = pack_hilo(v11);
                } else {
                    float* out = (float*)outv;
                    out[o0 + pcb]     = v00;
                    out[o1 + pcb]     = v01;
                    out[o0 + pcb + 4] = v10;
                    out[o1 + pcb + 4] = v11;
                }
            }
        }
    }
}

// ---------------- FC: [B,K] @ W[12,K]^T + b -> concat buffer ----------------
template <int K, bool RELU, bool USE_DOM>
__global__ void fc12_kernel(const float* __restrict__ x,
                            const float* __restrict__ Wbase,
                            const float* __restrict__ Bbase,
                            const int* __restrict__ dom_ptr,
                            float* __restrict__ out, int out_off)
{
    const int warp = threadIdx.x >> 5;
    const int lane = threadIdx.x & 31;
    const int b = blockIdx.x * 8 + warp;
    int dom = 0;
    if (USE_DOM) dom = dom_ptr[0];
    const float* W = Wbase + (size_t)dom * 12 * K;
    const float4* xr = reinterpret_cast<const float4*>(x + (size_t)b * K);

    float4 acc[12];
    #pragma unroll
    for (int j = 0; j < 12; j++) acc[j] = make_float4(0.f, 0.f, 0.f, 0.f);

    for (int k4 = lane; k4 < K / 4; k4 += 32) {
        float4 xv = xr[k4];
        #pragma unroll
        for (int j = 0; j < 12; j++) {
            float4 wv = reinterpret_cast<const float4*>(W + (size_t)j * K)[k4];
            acc[j].x = fmaf(xv.x, wv.x, acc[j].x);
            acc[j].y = fmaf(xv.y, wv.y, acc[j].y);
            acc[j].z = fmaf(xv.z, wv.z, acc[j].z);
            acc[j].w = fmaf(xv.w, wv.w, acc[j].w);
        }
    }
    const float* Bv = Bbase + dom * 12;
    #pragma unroll
    for (int j = 0; j < 12; j++) {
        float s = (acc[j].x + acc[j].y) + (acc[j].z + acc[j].w);
        #pragma unroll
        for (int o = 16; o > 0; o >>= 1) s += __shfl_xor_sync(0xffffffffu, s, o);
        if (lane == j) {
            float v = s + Bv[j];
            if (RELU) v = fmaxf(v, 0.f);
            out[b * 24 + out_off + j] = v;
        }
    }
}

// ---------------- per-sample routed heads: 24 -> 28 -> 14 -> 5 ----------------
__global__ void heads_kernel(const float* __restrict__ x24,
                             const int* __restrict__ tt,
                             const float* __restrict__ W1, const float* __restrict__ b1,
                             const float* __restrict__ W2, const float* __restrict__ b2,
                             const float* __restrict__ W3, const float* __restrict__ b3,
                             float* __restrict__ out)
{
    const int warp = threadIdx.x >> 5;
    const int lane = threadIdx.x & 31;
    const int b = blockIdx.x * 8 + warp;
    const int t = tt[b];

    float xv = (lane < 24) ? x24[b * 24 + lane] : 0.f;

    const float* w1 = W1 + t * 28 * 24 + min(lane, 27) * 24;
    float h1 = 0.f;
    #pragma unroll
    for (int k = 0; k < 24; k++)
        h1 = fmaf(w1[k], __shfl_sync(0xffffffffu, xv, k), h1);
    if (lane < 28) h1 += b1[t * 28 + lane];
    h1 = fmaxf(h1, 0.f);
    if (lane >= 28) h1 = 0.f;

    const float* w2 = W2 + t * 14 * 28 + min(lane, 13) * 28;
    float h2 = 0.f;
    #pragma unroll
    for (int k = 0; k < 28; k++)
        h2 = fmaf(w2[k], __shfl_sync(0xffffffffu, h1, k), h2);
    if (lane < 14) h2 += b2[t * 14 + lane];
    h2 = fmaxf(h2, 0.f);
    if (lane >= 14) h2 = 0.f;

    const float* w3 = W3 + t * 5 * 14 + min(lane, 4) * 14;
    float o = 0.f;
    #pragma unroll
    for (int k = 0; k < 14; k++)
        o = fmaf(w3[k], __shfl_sync(0xffffffffu, h2, k), o);
    if (lane < 5) out[b * 5 + lane] = o + b3[t * 5 + lane];
}

// ---------------- launch ----------------
extern "C" void kernel_launch(void* const* d_in, const int* in_sizes, int n_in,
                              void* d_out, int out_size)
{
    const float* x_s = (const float*)d_in[0];
    const float* x_p = (const float*)d_in[1];
    const int*   tt  = (const int*)d_in[2];
    const int*   dom = (const int*)d_in[3];
    const float* WsW = (const float*)d_in[4];
    const float* Wsb = (const float*)d_in[5];
    const float* WhW = (const float*)d_in[6];
    const float* Whb = (const float*)d_in[7];
    const float* WfW = (const float*)d_in[8];
    const float* Wfb = (const float*)d_in[9];
    const float* PcW = (const float*)d_in[10];
    const float* Pcb = (const float*)d_in[11];
    const float* PlW = (const float*)d_in[12];
    const float* Plb = (const float*)d_in[13];
    const float* H1W = (const float*)d_in[14];
    const float* H1b = (const float*)d_in[15];
    const float* H2W = (const float*)d_in[16];
    const float* H2b = (const float*)d_in[17];
    const float* H3W = (const float*)d_in[18];
    const float* H3b = (const float*)d_in[19];
    float* out = (float*)d_out;
    const int B = in_sizes[2];  // 1024

    unsigned *s1, *s2;
    float *s3, *p1, *x24, *Wf, *Wc1, *Wp;
    cudaGetSymbolAddress((void**)&s1,  g_s1);
    cudaGetSymbolAddress((void**)&s2,  g_s2);
    cudaGetSymbolAddress((void**)&s3,  g_s3);
    cudaGetSymbolAddress((void**)&p1,  g_p1);
    cudaGetSymbolAddress((void**)&x24, g_x24);
    cudaGetSymbolAddress((void**)&Wf,  g_Wf);
    cudaGetSymbolAddress((void**)&Wc1, g_Wc1);
    cudaGetSymbolAddress((void**)&Wp,  g_Wp);

    const size_t smb  = (size_t)(40 * 360 + 2 * 480 * 4) * sizeof(unsigned);   // 73.0 KB
    const size_t smc1 = (size_t)(8 * 456) * sizeof(unsigned);                   // 14.6 KB

    cudaFuncSetAttribute(bfconv_kernel<32, 4, 36, 8, true>,
                         cudaFuncAttributeMaxDynamicSharedMemorySize, (int)smb);
    cudaFuncSetAttribute(bfconv_kernel<16, 1, 20, 8, false>,
                         cudaFuncAttributeMaxDynamicSharedMemorySize, (int)smb);

    // fragment-ready weights (tiny; every launch, deterministic)
    wprep_kernel<<<(9 * 5 * 3 * 32 + 127) / 128, 128>>>(WhW, Wf);
    wprep3_kernel<36, 3, false><<<(9 * 3 * 32 + 127) / 128, 128>>>(WsW, nullptr, Wc1);
    wprep3_kernel<12, 1, true ><<<(9 * 1 * 32 + 127) / 128, 128>>>(PcW, dom, Wp);

    // shared branch
    bf3conv_kernel<36, 3, 5, false, false, true>
        <<<dim3(16, B), 256, smc1>>>(x_s, Wc1, Wsb, nullptr, s1);
    bfconv_kernel<32, 4, 36, 8, true ><<<dim3(4, B), 256, smb>>>(s1, Wf, Whb, s2);
    bfconv_kernel<16, 1, 20, 8, false><<<dim3(1, B), 256, smb>>>(s2, Wf, Whb, s3);
    // private branch
    bf3conv_kernel<12, 1, 2, true, true, false>
        <<<dim3(16, B), 256, smc1>>>(x_p, Wp, Pcb, dom, p1);
    // FCs -> concat buffer
    fc12_kernel<2304,  true,  false><<<B / 8, 256>>>(s3, WfW, Wfb, nullptr, x24, 0);
    fc12_kernel<12288, false, true ><<<B / 8, 256>>>(p1, PlW, Plb, dom,     x24, 12);
    // routed heads -> output
    heads_kernel<<<B / 8, 256>>>(x24, tt, H1W, H1b, H2W, H2b, H3W, H3b, out);
}

// round 14
// speedup vs baseline: 1.5594x; 1.5594x over previous
#include <cuda_runtime.h>
#include <cuda_bf16.h>
#include <cstdint>

// ---------------- scratch (device globals; no allocation allowed) ----------------
__device__ unsigned g_s1[1024 * 36 * 32 * 32]; // conv1 out, packed bf16x2(hi,lo)
__device__ unsigned g_s2[1024 * 36 * 16 * 16]; // conv2 out, packed bf16x2(hi,lo)
__device__ float    g_s3[1024 * 36 * 8 * 8];   // conv3 out (fp32, feeds FC)
__device__ float    g_p1[1024 * 12 * 32 * 32]; // private conv out
__device__ float    g_x24[1024 * 24];          // concat [h | p]
__device__ float    g_Wf[9 * 5 * 3 * 32 * 4];  // hidden conv frag weights, ord0 (69 KB)

// ---------------- packing helpers ----------------
__device__ __forceinline__ unsigned pack_hilo(float v) {
    __nv_bfloat16 h = __float2bfloat16_rn(v);
    float hf = __bfloat162float(h);
    __nv_bfloat16 l = __float2bfloat16_rn(v - hf);
    return (((unsigned)__bfloat16_as_ushort(l)) << 16) | (unsigned)__bfloat16_as_ushort(h);
}
__device__ __forceinline__ unsigned rot16(unsigned w) {   // swap 16-bit halves
    return (w << 16) | (w >> 16);
}

// NOT volatile: pure register op. Lets ptxas schedule/reorder HMMAs to break
// same-accumulator dependency stalls (the volatile version pinned tensor% at ~55).
__device__ __forceinline__ void mma_bf16(float* d, const unsigned* a, unsigned b0, unsigned b1) {
    asm("mma.sync.aligned.m16n8k16.row.col.f32.bf16.bf16.f32 "
        "{%0,%1,%2,%3}, {%4,%5,%6,%7}, {%8,%9}, {%0,%1,%2,%3};"
        : "+f"(d[0]), "+f"(d[1]), "+f"(d[2]), "+f"(d[3])
        : "r"(a[0]), "r"(a[1]), "r"(a[2]), "r"(a[3]), "r"(b0), "r"(b1));
}

// ---------------- weight prep (hidden convs): ord0 only ----------------
__global__ void wprep_kernel(const float* __restrict__ W, float* __restrict__ Wf)
{
    int idx = blockIdx.x * blockDim.x + threadIdx.x;
    if (idx >= 9 * 5 * 3 * 32) return;
    int lane = idx & 31;
    int q    = (idx >> 5) % 3;
    int kt   = (idx / 96) % 5;
    int tap  = idx / 480;
    int km = lane & 3, n = lane >> 2;
    int ci0 = kt * 8 + km, ci1 = ci0 + 4;
    int oc0 = q * 16 + n,  oc1 = oc0 + 8;
    auto pk = [&](int ci, int oc) -> float {
        float w = 0.f;
        if (ci < 36 && oc < 36) w = W[((size_t)oc * 36 + ci) * 9 + tap];
        return __uint_as_float(pack_hilo(w));
    };
    float4 f;
    f.x = pk(ci0, oc0); f.y = pk(ci1, oc0);
    f.z = pk(ci0, oc1); f.w = pk(ci1, oc1);
    reinterpret_cast<float4*>(Wf)[idx] = f;
}

// ---------------- bf16-split implicit-GEMM conv3x3 + relu + maxpool2 (hidden) --------
// R11 structure (double-buffered per-tap B in smem, zero-LDG mainloop) with the MMA
// stream split into two passes so same-accumulator reuse distance is 10, not 1.
template <int S, int STRIPS, int P, int NWARPS, bool OUTPACK>
__global__ void __launch_bounds__(NWARPS * 32)
bfconv_kernel(const unsigned* __restrict__ x, const float* __restrict__ Wf,
              const float* __restrict__ Bv, void* __restrict__ outv)
{
    constexpr int NT  = NWARPS * 32;
    constexpr int SR  = S / STRIPS;
    constexpr int PH  = SR + 2;
    constexpr int PHP = PH * P;
    static_assert(PHP % 32 == 8, "bank layout");
    constexpr int RPAIRS = SR / 2;
    constexpr int COLT   = S / 16;
    static_assert(RPAIRS * COLT == NWARPS, "warp count");
    constexpr int Sp = S / 2;
    constexpr int WTAP = 5 * 3 * 32;

    extern __shared__ unsigned sx[];
    float4* sB = reinterpret_cast<float4*>(sx + 40 * PHP);   // [2][WTAP]

    const int strip = blockIdx.x;
    const int b     = blockIdx.y;
    const int tid   = threadIdx.x;
    const int w     = tid >> 5;
    const int lane  = tid & 31;

    for (int i = tid; i < 40 * PHP; i += NT) sx[i] = 0u;
    __syncthreads();

    const int r0  = strip * SR;
    const int gr0 = (r0 - 1 < 0) ? 0 : r0 - 1;
    const int gr1 = (r0 + SR + 1 > S) ? S : r0 + SR + 1;
    const int nrow = gr1 - gr0;
    const unsigned* xb = x + (size_t)b * 36 * S * S;
    for (int i = tid; i < 36 * nrow * S; i += NT) {
        int ci = i / (nrow * S);
        int rr = (i / S) % nrow;
        int c  = i % S;
        int gr = gr0 + rr;
        sx[ci * PHP + (gr - r0 + 1) * P + (c + 1)] = xb[ci * S * S + gr * S + c];
    }
    const float4* Wf4 = reinterpret_cast<const float4*>(Wf);
    for (int i = tid; i < WTAP; i += NT) sB[i] = __ldg(Wf4 + i);
    __syncthreads();

    const int rp  = w / COLT;
    const int c0  = (w % COLT) * 16;
    const int lr0 = 2 * rp;
    const int la  = lane & 3;
    const int lg  = lane >> 2;

    float C[5][2][4];
    #pragma unroll
    for (int n = 0; n < 5; n++)
        #pragma unroll
        for (int t = 0; t < 2; t++)
            #pragma unroll
            for (int j = 0; j < 4; j++) C[n][t][j] = 0.f;

    const int aoff0 = la * PHP + lr0 * P + c0 + lg;

    for (int tap = 0; tap < 9; tap++) {
        const int p = tap & 1;
        if (tap + 1 < 9) {
            const float4* src = Wf4 + (tap + 1) * WTAP;
            for (int i = tid; i < WTAP; i += NT) sB[(p ^ 1) * WTAP + i] = __ldg(src + i);
        }

        const int dy = tap / 3, dx = tap % 3;
        const int abase = aoff0 + dy * P + dx;
        const float4* bt = sB + p * WTAP;

        #pragma unroll
        for (int kt = 0; kt < 5; kt++) {
            unsigned A[2][4];
            #pragma unroll
            for (int t = 0; t < 2; t++) {
                const unsigned* ap = sx + abase + t * P + kt * 8 * PHP;
                A[t][0] = ap[0];
                A[t][1] = ap[8];
                A[t][2] = ap[4 * PHP];
                A[t][3] = ap[4 * PHP + 8];
            }
            float4 q0 = bt[kt * 96 + 0 * 32 + lane];
            float4 q1 = bt[kt * 96 + 1 * 32 + lane];
            float4 q2 = bt[kt * 96 + 2 * 32 + lane];

            unsigned Bw[5][2] = {
                {__float_as_uint(q0.x), __float_as_uint(q0.y)},
                {__float_as_uint(q0.z), __float_as_uint(q0.w)},
                {__float_as_uint(q1.x), __float_as_uint(q1.y)},
                {__float_as_uint(q1.z), __float_as_uint(q1.w)},
                {__float_as_uint(q2.x), __float_as_uint(q2.y)} };
            unsigned Br[5][2];
            #pragma unroll
            for (int n = 0; n < 5; n++) {
                Br[n][0] = rot16(Bw[n][0]);
                Br[n][1] = rot16(Bw[n][1]);
            }

            // pass 1: ord0 words (ahbh + albl) — 10 independent accumulators
            #pragma unroll
            for (int n = 0; n < 5; n++)
                #pragma unroll
                for (int t = 0; t < 2; t++)
                    mma_bf16(C[n][t], A[t], Bw[n][0], Bw[n][1]);
            // pass 2: rotated words (ahbl + albh) — reuse distance 10
            #pragma unroll
            for (int n = 0; n < 5; n++)
                #pragma unroll
                for (int t = 0; t < 2; t++)
                    mma_bf16(C[n][t], A[t], Br[n][0], Br[n][1]);
        }
        __syncthreads();
    }

    const int pr = strip * RPAIRS + rp;
    #pragma unroll
    for (int n = 0; n < 5; n++) {
        float m0 = fmaxf(C[n][0][0], C[n][1][0]);
        float m1 = fmaxf(C[n][0][1], C[n][1][1]);
        float m2 = fmaxf(C[n][0][2], C[n][1][2]);
        float m3 = fmaxf(C[n][0][3], C[n][1][3]);
        float p0 = fmaxf(m0, __shfl_xor_sync(0xffffffffu, m0, 4));
        float p1 = fmaxf(m1, __shfl_xor_sync(0xffffffffu, m1, 4));
        float p2 = fmaxf(m2, __shfl_xor_sync(0xffffffffu, m2, 4));
        float p3 = fmaxf(m3, __shfl_xor_sync(0xffffffffu, m3, 4));
        if ((lane & 4) == 0) {
            int oc0 = n * 8 + (lane & 3) * 2;
            if (oc0 < 36) {
                int pcb = c0 / 2 + ((lane >> 3) & 3);
                float b0 = __ldg(Bv + oc0);
                float b1 = __ldg(Bv + oc0 + 1);
                float v00 = fmaxf(p0 + b0, 0.f);
                float v01 = fmaxf(p1 + b1, 0.f);
                float v10 = fmaxf(p2 + b0, 0.f);
                float v11 = fmaxf(p3 + b1, 0.f);
                size_t o0 = (((size_t)b * 36 + oc0) * Sp + pr) * Sp;
                size_t o1 = o0 + (size_t)Sp * Sp;
                if (OUTPACK) {
                    unsigned* out = (unsigned*)outv;
                    out[o0 + pcb]     = pack_hilo(v00);
                    out[o1 + pcb]     = pack_hilo(v01);
                    out[o0 + pcb + 4] = pack_hilo(v10);
                    out[o1 + pcb + 4] = pack_hilo(v11);
                } else {
                    float* out = (float*)outv;
                    out[o0 + pcb]     = v00;
                    out[o1 + pcb]     = v01;
                    out[o0 + pcb + 4] = v10;
                    out[o1 + pcb + 4] = v11;
                }
            }
        }
    }
}

// ---------------- direct conv3x3 + act + maxpool2 (3-channel layers, fp32) -----------
template <int IC, int OC, int S, bool LEAKY, bool USE_DOM, bool OUTPACK, int NT>
__global__ void __launch_bounds__(NT)
convpool_kernel(const float* __restrict__ x,
                const float* __restrict__ Wbase,
                const float* __restrict__ Bbase,
                const int* __restrict__ dom_ptr,
                void* __restrict__ outv)
{
    constexpr int PH = S + 2;
    constexpr int P  = S + 4;
    constexpr int HT = S / 4;
    constexpr int Sp = S / 2;
    extern __shared__ float smem[];
    float* sx = smem;
    float* sw = smem + IC * PH * P;

    const int b   = blockIdx.x;
    const int tid = threadIdx.x;

    int dom = 0;
    if (USE_DOM) dom = dom_ptr[0];
    const float* W  = Wbase + (size_t)dom * OC * IC * 9;
    const float* Bv = Bbase + (size_t)dom * OC;

    for (int i = tid; i < IC * PH * P; i += NT) sx[i] = 0.f;
    __syncthreads();
    const float* xb = x + (size_t)b * IC * S * S;
    for (int i = tid; i < IC * S * S; i += NT) {
        int c  = i / (S * S);
        int r  = (i / S) % S;
        int cc = i % S;
        sx[c * PH * P + (r + 1) * P + (cc + 1)] = xb[i];
    }
    for (int i = tid; i < OC * IC * 9; i += NT) sw[i] = W[i];
    __syncthreads();

    constexpr int tilesPerOc = HT * HT;
    constexpr int tiles = OC * tilesPerOc;
    for (int t = tid; t < tiles; t += NT) {
        int oc  = t / tilesPerOc;
        int rem = t - oc * tilesPerOc;
        int ty  = rem / HT;
        int tx  = rem - ty * HT;

        float acc[16];
        #pragma unroll
        for (int i = 0; i < 16; i++) acc[i] = 0.f;

        const float* wp    = sw + oc * IC * 9;
        const float* xbase = sx + (4 * ty) * P + 4 * tx;

        for (int ci = 0; ci < IC; ci++) {
            const float* xp = xbase + ci * PH * P;
            float w0 = wp[0], w1 = wp[1], w2 = wp[2],
                  w3 = wp[3], w4 = wp[4], w5 = wp[5],
                  w6 = wp[6], w7 = wp[7], w8 = wp[8];
            wp += 9;
            float p[6][6];
            #pragma unroll
            for (int r = 0; r < 6; r++) {
                float4 a  = *reinterpret_cast<const float4*>(xp + r * P);
                float4 bq = *reinterpret_cast<const float4*>(xp + r * P + 4);
                p[r][0] = a.x;  p[r][1] = a.y;  p[r][2] = a.z;  p[r][3] = a.w;
                p[r][4] = bq.x; p[r][5] = bq.y;
            }
            #pragma unroll
            for (int r = 0; r < 4; r++) {
                #pragma unroll
                for (int c = 0; c < 4; c++) {
                    float s = acc[r * 4 + c];
                    s = fmaf(w0, p[r][c],         s);
                    s = fmaf(w1, p[r][c + 1],     s);
                    s = fmaf(w2, p[r][c + 2],     s);
                    s = fmaf(w3, p[r + 1][c],     s);
                    s = fmaf(w4, p[r + 1][c + 1], s);
                    s = fmaf(w5, p[r + 1][c + 2], s);
                    s = fmaf(w6, p[r + 2][c],     s);
                    s = fmaf(w7, p[r + 2][c + 1], s);
                    s = fmaf(w8, p[r + 2][c + 2], s);
                    acc[r * 4 + c] = s;
                }
            }
        }
        float bias = Bv[oc];
        size_t ob = (((size_t)b * OC + oc) * Sp + 2 * ty) * Sp + 2 * tx;
        #pragma unroll
        for (int pr = 0; pr < 2; pr++) {
            #pragma unroll
            for (int pc = 0; pc < 2; pc++) {
                float m = fmaxf(fmaxf(acc[(2*pr)*4 + 2*pc],   acc[(2*pr)*4 + 2*pc + 1]),
                                fmaxf(acc[(2*pr+1)*4 + 2*pc], acc[(2*pr+1)*4 + 2*pc + 1]));
                m += bias;
                float v;
                if (LEAKY) v = (m > 0.f) ? m : 0.001f * m;
                else       v = fmaxf(m, 0.f);
                if (OUTPACK) ((unsigned*)outv)[ob + pr * Sp + pc] = pack_hilo(v);
                else         ((float*)outv)[ob + pr * Sp + pc] = v;
            }
        }
    }
}

// ---------------- FC: [B,K] @ W[12,K]^T + b -> concat buffer ----------------
template <int K, bool RELU, bool USE_DOM>
__global__ void fc12_kernel(const float* __restrict__ x,
                            const float* __restrict__ Wbase,
                            const float* __restrict__ Bbase,
                            const int* __restrict__ dom_ptr,
                            float* __restrict__ out, int out_off)
{
    const int warp = threadIdx.x >> 5;
    const int lane = threadIdx.x & 31;
    const int b = blockIdx.x * 8 + warp;
    int dom = 0;
    if (USE_DOM) dom = dom_ptr[0];
    const float* W = Wbase + (size_t)dom * 12 * K;
    const float4* xr = reinterpret_cast<const float4*>(x + (size_t)b * K);

    float4 acc[12];
    #pragma unroll
    for (int j = 0; j < 12; j++) acc[j] = make_float4(0.f, 0.f, 0.f, 0.f);

    for (int k4 = lane; k4 < K / 4; k4 += 32) {
        float4 xv = xr[k4];
        #pragma unroll
        for (int j = 0; j < 12; j++) {
            float4 wv = reinterpret_cast<const float4*>(W + (size_t)j * K)[k4];
            acc[j].x = fmaf(xv.x, wv.x, acc[j].x);
            acc[j].y = fmaf(xv.y, wv.y, acc[j].y);
            acc[j].z = fmaf(xv.z, wv.z, acc[j].z);
            acc[j].w = fmaf(xv.w, wv.w, acc[j].w);
        }
    }
    const float* Bv = Bbase + dom * 12;
    #pragma unroll
    for (int j = 0; j < 12; j++) {
        float s = (acc[j].x + acc[j].y) + (acc[j].z + acc[j].w);
        #pragma unroll
        for (int o = 16; o > 0; o >>= 1) s += __shfl_xor_sync(0xffffffffu, s, o);
        if (lane == j) {
            float v = s + Bv[j];
            if (RELU) v = fmaxf(v, 0.f);
            out[b * 24 + out_off + j] = v;
        }
    }
}

// ---------------- per-sample routed heads: 24 -> 28 -> 14 -> 5 ----------------
__global__ void heads_kernel(const float* __restrict__ x24,
                             const int* __restrict__ tt,
                             const float* __restrict__ W1, const float* __restrict__ b1,
                             const float* __restrict__ W2, const float* __restrict__ b2,
                             const float* __restrict__ W3, const float* __restrict__ b3,
                             float* __restrict__ out)
{
    const int warp = threadIdx.x >> 5;
    const int lane = threadIdx.x & 31;
    const int b = blockIdx.x * 8 + warp;
    const int t = tt[b];

    float xv = (lane < 24) ? x24[b * 24 + lane] : 0.f;

    const float* w1 = W1 + t * 28 * 24 + min(lane, 27) * 24;
    float h1 = 0.f;
    #pragma unroll
    for (int k = 0; k < 24; k++)
        h1 = fmaf(w1[k], __shfl_sync(0xffffffffu, xv, k), h1);
    if (lane < 28) h1 += b1[t * 28 + lane];
    h1 = fmaxf(h1, 0.f);
    if (lane >= 28) h1 = 0.f;

    const float* w2 = W2 + t * 14 * 28 + min(lane, 13) * 28;
    float h2 = 0.f;
    #pragma unroll
    for (int k = 0; k < 28; k++)
        h2 = fmaf(w2[k], __shfl_sync(0xffffffffu, h1, k), h2);
    if (lane < 14) h2 += b2[t * 14 + lane];
    h2 = fmaxf(h2, 0.f);
    if (lane >= 14) h2 = 0.f;

    const float* w3 = W3 + t * 5 * 14 + min(lane, 4) * 14;
    float o = 0.f;
    #pragma unroll
    for (int k = 0; k < 14; k++)
        o = fmaf(w3[k], __shfl_sync(0xffffffffu, h2, k), o);
    if (lane < 5) out[b * 5 + lane] = o + b3[t * 5 + lane];
}

// ---------------- launch ----------------
extern "C" void kernel_launch(void* const* d_in, const int* in_sizes, int n_in,
                              void* d_out, int out_size)
{
    const float* x_s = (const float*)d_in[0];
    const float* x_p = (const float*)d_in[1];
    const int*   tt  = (const int*)d_in[2];
    const int*   dom = (const int*)d_in[3];
    const float* WsW = (const float*)d_in[4];
    const float* Wsb = (const float*)d_in[5];
    const float* WhW = (const float*)d_in[6];
    const float* Whb = (const float*)d_in[7];
    const float* WfW = (const float*)d_in[8];
    const float* Wfb = (const float*)d_in[9];
    const float* PcW = (const float*)d_in[10];
    const float* Pcb = (const float*)d_in[11];
    const float* PlW = (const float*)d_in[12];
    const float* Plb = (const float*)d_in[13];
    const float* H1W = (const float*)d_in[14];
    const float* H1b = (const float*)d_in[15];
    const float* H2W = (const float*)d_in[16];
    const float* H2b = (const float*)d_in[17];
    const float* H3W = (const float*)d_in[18];
    const float* H3b = (const float*)d_in[19];
    float* out = (float*)d_out;
    const int B = in_sizes[2];  // 1024

    unsigned *s1, *s2;
    float *s3, *p1, *x24, *Wf;
    cudaGetSymbolAddress((void**)&s1,  g_s1);
    cudaGetSymbolAddress((void**)&s2,  g_s2);
    cudaGetSymbolAddress((void**)&s3,  g_s3);
    cudaGetSymbolAddress((void**)&p1,  g_p1);
    cudaGetSymbolAddress((void**)&x24, g_x24);
    cudaGetSymbolAddress((void**)&Wf,  g_Wf);

    const size_t sm1  = (size_t)(3 * 66 * 68 + 36 * 3 * 9) * sizeof(float);
    const size_t smp  = (size_t)(3 * 66 * 68 + 12 * 3 * 9) * sizeof(float);
    const size_t smb  = (size_t)(40 * 360 + 2 * 480 * 4) * sizeof(unsigned);   // 73.0 KB

    cudaFuncSetAttribute(convpool_kernel<3, 36, 64, false, false, true, 256>,
                         cudaFuncAttributeMaxDynamicSharedMemorySize, (int)sm1);
    cudaFuncSetAttribute(convpool_kernel<3, 12, 64, true, true, false, 256>,
                         cudaFuncAttributeMaxDynamicSharedMemorySize, (int)smp);
    cudaFuncSetAttribute(bfconv_kernel<32, 4, 36, 8, true>,
                         cudaFuncAttributeMaxDynamicSharedMemorySize, (int)smb);
    cudaFuncSetAttribute(bfconv_kernel<16, 1, 20, 8, false>,
                         cudaFuncAttributeMaxDynamicSharedMemorySize, (int)smb);

    // fragment-ready split weights, ord0 only (tiny; every launch, deterministic)
    wprep_kernel<<<(9 * 5 * 3 * 32 + 127) / 128, 128>>>(WhW, Wf);

    // shared branch
    convpool_kernel<3, 36, 64, false, false, true, 256>
        <<<B, 256, sm1>>>(x_s, WsW, Wsb, nullptr, s1);
    bfconv_kernel<32, 4, 36, 8, true ><<<dim3(4, B), 256, smb>>>(s1, Wf, Whb, s2);
    bfconv_kernel<16, 1, 20, 8, false><<<dim3(1, B), 256, smb>>>(s2, Wf, Whb, s3);
    // private branch
    convpool_kernel<3, 12, 64, true, true, false, 256>
        <<<B, 256, smp>>>(x_p, PcW, Pcb, dom, p1);
    // FCs -> concat buffer
    fc12_kernel<2304,  true,  false><<<B / 8, 256>>>(s3, WfW, Wfb, nullptr, x24, 0);
    fc12_kernel<12288, false, true ><<<B / 8, 256>>>(p1, PlW, Plb, dom,     x24, 12);
    // routed heads -> output
    heads_kernel<<<B / 8, 256>>>(x24, tt, H1W, H1b, H2W, H2b, H3W, H3b, out);
}

// round 15
// speedup vs baseline: 1.6177x; 1.0374x over previous
#include <cuda_runtime.h>
#include <cuda_bf16.h>
#include <cstdint>

// ---------------- scratch (device globals; no allocation allowed) ----------------
__device__ unsigned g_s1[1024 * 36 * 32 * 32]; // conv1 out, packed bf16x2(hi,lo)
__device__ unsigned g_s2[1024 * 36 * 16 * 16]; // conv2 out, packed bf16x2(hi,lo)
__device__ float    g_s3[1024 * 36 * 8 * 8];   // conv3 out (fp32, feeds FC)
__device__ float    g_p1[1024 * 12 * 32 * 32]; // private conv out
__device__ float    g_x24[1024 * 24];          // concat [h | p]
__device__ float    g_Wf[9 * 5 * 3 * 32 * 4];  // hidden conv frag weights, ord0 (69 KB)

// ---------------- packing helpers ----------------
__device__ __forceinline__ unsigned pack_hilo(float v) {
    __nv_bfloat16 h = __float2bfloat16_rn(v);
    float hf = __bfloat162float(h);
    __nv_bfloat16 l = __float2bfloat16_rn(v - hf);
    return (((unsigned)__bfloat16_as_ushort(l)) << 16) | (unsigned)__bfloat16_as_ushort(h);
}
__device__ __forceinline__ unsigned rot16(unsigned w) {   // swap 16-bit halves
    return (w << 16) | (w >> 16);
}

__device__ __forceinline__ void mma_bf16(float* d, const unsigned* a, unsigned b0, unsigned b1) {
    asm("mma.sync.aligned.m16n8k16.row.col.f32.bf16.bf16.f32 "
        "{%0,%1,%2,%3}, {%4,%5,%6,%7}, {%8,%9}, {%0,%1,%2,%3};"
        : "+f"(d[0]), "+f"(d[1]), "+f"(d[2]), "+f"(d[3])
        : "r"(a[0]), "r"(a[1]), "r"(a[2]), "r"(a[3]), "r"(b0), "r"(b1));
}

// ---------------- weight prep (hidden convs): ord0 only ----------------
__global__ void wprep_kernel(const float* __restrict__ W, float* __restrict__ Wf)
{
    int idx = blockIdx.x * blockDim.x + threadIdx.x;
    if (idx >= 9 * 5 * 3 * 32) return;
    int lane = idx & 31;
    int q    = (idx >> 5) % 3;
    int kt   = (idx / 96) % 5;
    int tap  = idx / 480;
    int km = lane & 3, n = lane >> 2;
    int ci0 = kt * 8 + km, ci1 = ci0 + 4;
    int oc0 = q * 16 + n,  oc1 = oc0 + 8;
    auto pk = [&](int ci, int oc) -> float {
        float w = 0.f;
        if (ci < 36 && oc < 36) w = W[((size_t)oc * 36 + ci) * 9 + tap];
        return __uint_as_float(pack_hilo(w));
    };
    float4 f;
    f.x = pk(ci0, oc0); f.y = pk(ci1, oc0);
    f.z = pk(ci0, oc1); f.w = pk(ci1, oc1);
    reinterpret_cast<float4*>(Wf)[idx] = f;
}

// ---------------- bf16-split implicit-GEMM conv3x3 + relu + maxpool2 (hidden) --------
// R14 mainloop; staging vectorized to uint4 loads (4x fewer prologue LDGs).
template <int S, int STRIPS, int P, int NWARPS, bool OUTPACK>
__global__ void __launch_bounds__(NWARPS * 32)
bfconv_kernel(const unsigned* __restrict__ x, const float* __restrict__ Wf,
              const float* __restrict__ Bv, void* __restrict__ outv)
{
    constexpr int NT  = NWARPS * 32;
    constexpr int SR  = S / STRIPS;
    constexpr int PH  = SR + 2;
    constexpr int PHP = PH * P;
    static_assert(PHP % 32 == 8, "bank layout");
    constexpr int RPAIRS = SR / 2;
    constexpr int COLT   = S / 16;
    static_assert(RPAIRS * COLT == NWARPS, "warp count");
    constexpr int Sp = S / 2;
    constexpr int WTAP = 5 * 3 * 32;

    extern __shared__ unsigned sx[];
    float4* sB = reinterpret_cast<float4*>(sx + 40 * PHP);   // [2][WTAP]

    const int strip = blockIdx.x;
    const int b     = blockIdx.y;
    const int tid   = threadIdx.x;
    const int w     = tid >> 5;
    const int lane  = tid & 31;

    // vectorized zero-fill (40*PHP multiple of 4, base 16B-aligned)
    {
        uint4 z = make_uint4(0u, 0u, 0u, 0u);
        uint4* sz = reinterpret_cast<uint4*>(sx);
        for (int i = tid; i < 40 * PHP / 4; i += NT) sz[i] = z;
    }
    __syncthreads();

    const int r0  = strip * SR;
    const int gr0 = (r0 - 1 < 0) ? 0 : r0 - 1;
    const int gr1 = (r0 + SR + 1 > S) ? S : r0 + SR + 1;
    const int nrow = gr1 - gr0;
    const unsigned* xb = x + (size_t)b * 36 * S * S;
    // vectorized staging: each thread moves 4 consecutive words per step
    for (int i4 = tid; i4 < 36 * nrow * S / 4; i4 += NT) {
        int i  = i4 * 4;
        int ci = i / (nrow * S);
        int rr = (i / S) % nrow;
        int c  = i % S;                 // multiple of 4 (S % 4 == 0)
        int gr = gr0 + rr;
        uint4 v = *reinterpret_cast<const uint4*>(xb + ci * S * S + gr * S + c);
        unsigned* d = sx + ci * PHP + (gr - r0 + 1) * P + c + 1;
        d[0] = v.x; d[1] = v.y; d[2] = v.z; d[3] = v.w;
    }
    const float4* Wf4 = reinterpret_cast<const float4*>(Wf);
    for (int i = tid; i < WTAP; i += NT) sB[i] = __ldg(Wf4 + i);
    __syncthreads();

    const int rp  = w / COLT;
    const int c0  = (w % COLT) * 16;
    const int lr0 = 2 * rp;
    const int la  = lane & 3;
    const int lg  = lane >> 2;

    float C[5][2][4];
    #pragma unroll
    for (int n = 0; n < 5; n++)
        #pragma unroll
        for (int t = 0; t < 2; t++)
            #pragma unroll
            for (int j = 0; j < 4; j++) C[n][t][j] = 0.f;

    const int aoff0 = la * PHP + lr0 * P + c0 + lg;

    for (int tap = 0; tap < 9; tap++) {
        const int p = tap & 1;
        if (tap + 1 < 9) {
            const float4* src = Wf4 + (tap + 1) * WTAP;
            for (int i = tid; i < WTAP; i += NT) sB[(p ^ 1) * WTAP + i] = __ldg(src + i);
        }

        const int dy = tap / 3, dx = tap % 3;
        const int abase = aoff0 + dy * P + dx;
        const float4* bt = sB + p * WTAP;

        #pragma unroll
        for (int kt = 0; kt < 5; kt++) {
            unsigned A[2][4];
            #pragma unroll
            for (int t = 0; t < 2; t++) {
                const unsigned* ap = sx + abase + t * P + kt * 8 * PHP;
                A[t][0] = ap[0];
                A[t][1] = ap[8];
                A[t][2] = ap[4 * PHP];
                A[t][3] = ap[4 * PHP + 8];
            }
            float4 q0 = bt[kt * 96 + 0 * 32 + lane];
            float4 q1 = bt[kt * 96 + 1 * 32 + lane];
            float4 q2 = bt[kt * 96 + 2 * 32 + lane];

            unsigned Bw[5][2] = {
                {__float_as_uint(q0.x), __float_as_uint(q0.y)},
                {__float_as_uint(q0.z), __float_as_uint(q0.w)},
                {__float_as_uint(q1.x), __float_as_uint(q1.y)},
                {__float_as_uint(q1.z), __float_as_uint(q1.w)},
                {__float_as_uint(q2.x), __float_as_uint(q2.y)} };
            unsigned Br[5][2];
            #pragma unroll
            for (int n = 0; n < 5; n++) {
                Br[n][0] = rot16(Bw[n][0]);
                Br[n][1] = rot16(Bw[n][1]);
            }

            #pragma unroll
            for (int n = 0; n < 5; n++)
                #pragma unroll
                for (int t = 0; t < 2; t++)
                    mma_bf16(C[n][t], A[t], Bw[n][0], Bw[n][1]);
            #pragma unroll
            for (int n = 0; n < 5; n++)
                #pragma unroll
                for (int t = 0; t < 2; t++)
                    mma_bf16(C[n][t], A[t], Br[n][0], Br[n][1]);
        }
        __syncthreads();
    }

    const int pr = strip * RPAIRS + rp;
    #pragma unroll
    for (int n = 0; n < 5; n++) {
        float m0 = fmaxf(C[n][0][0], C[n][1][0]);
        float m1 = fmaxf(C[n][0][1], C[n][1][1]);
        float m2 = fmaxf(C[n][0][2], C[n][1][2]);
        float m3 = fmaxf(C[n][0][3], C[n][1][3]);
        float p0 = fmaxf(m0, __shfl_xor_sync(0xffffffffu, m0, 4));
        float p1 = fmaxf(m1, __shfl_xor_sync(0xffffffffu, m1, 4));
        float p2 = fmaxf(m2, __shfl_xor_sync(0xffffffffu, m2, 4));
        float p3 = fmaxf(m3, __shfl_xor_sync(0xffffffffu, m3, 4));
        if ((lane & 4) == 0) {
            int oc0 = n * 8 + (lane & 3) * 2;
            if (oc0 < 36) {
                int pcb = c0 / 2 + ((lane >> 3) & 3);
                float b0 = __ldg(Bv + oc0);
                float b1 = __ldg(Bv + oc0 + 1);
                float v00 = fmaxf(p0 + b0, 0.f);
                float v01 = fmaxf(p1 + b1, 0.f);
                float v10 = fmaxf(p2 + b0, 0.f);
                float v11 = fmaxf(p3 + b1, 0.f);
                size_t o0 = (((size_t)b * 36 + oc0) * Sp + pr) * Sp;
                size_t o1 = o0 + (size_t)Sp * Sp;
                if (OUTPACK) {
                    unsigned* out = (unsigned*)outv;
                    out[o0 + pcb]     = pack_hilo(v00);
                    out[o1 + pcb]     = pack_hilo(v01);
                    out[o0 + pcb + 4] = pack_hilo(v10);
                    out[o1 + pcb + 4] = pack_hilo(v11);
                } else {
                    float* out = (float*)outv;
                    out[o0 + pcb]     = v00;
                    out[o1 + pcb]     = v01;
                    out[o0 + pcb + 4] = v10;
                    out[o1 + pcb + 4] = v11;
                }
            }
        }
    }
}

// ---------------- merged conv1 + private conv (fp32 direct, S=64, IC=3) --------------
// grid = (B, 2): y==0 -> shared conv1 (OC=36, relu, packed out),
//                y==1 -> private conv (OC=12, leaky, dom-selected, fp32 out).
// 2048 blocks instead of 2x1024 -> better wave packing + removes serialization.
__global__ void __launch_bounds__(256)
c1p_kernel(const float* __restrict__ x_s, const float* __restrict__ x_p,
           const float* __restrict__ WsW, const float* __restrict__ Wsb,
           const float* __restrict__ PcW, const float* __restrict__ Pcb,
           const int* __restrict__ dom_ptr,
           unsigned* __restrict__ s1, float* __restrict__ p1)
{
    constexpr int S = 64, PH = 66, P = 68, HT = 16, Sp = 32, NT = 256;
    extern __shared__ float smem[];
    float* sx = smem;                  // 3 * PH * P = 13464
    float* sw = smem + 3 * PH * P;     // up to 36*27

    const int b      = blockIdx.x;
    const int branch = blockIdx.y;     // 0 = shared, 1 = private
    const int tid    = threadIdx.x;

    const int OC = branch ? 12 : 36;
    int dom = branch ? dom_ptr[0] : 0;
    const float* x  = branch ? x_p : x_s;
    const float* W  = branch ? (PcW + (size_t)dom * 12 * 27) : WsW;
    const float* Bv = branch ? (Pcb + dom * 12) : Wsb;

    for (int i = tid; i < 3 * PH * P; i += NT) sx[i] = 0.f;
    __syncthreads();
    const float* xb = x + (size_t)b * 3 * S * S;
    for (int i4 = tid; i4 < 3 * S * S / 4; i4 += NT) {
        int i = i4 * 4;
        int c  = i / (S * S);
        int r  = (i / S) % S;
        int cc = i % S;                // multiple of 4
        float4 v = *reinterpret_cast<const float4*>(xb + i);
        float* d = sx + c * PH * P + (r + 1) * P + cc + 1;
        d[0] = v.x; d[1] = v.y; d[2] = v.z; d[3] = v.w;
    }
    for (int i = tid; i < OC * 27; i += NT) sw[i] = W[i];
    __syncthreads();

    const int tiles = OC * HT * HT;
    for (int t = tid; t < tiles; t += NT) {
        int oc  = t >> 8;              // /256
        int rem = t & 255;
        int ty  = rem >> 4;
        int tx  = rem & 15;

        float acc[16];
        #pragma unroll
        for (int i = 0; i < 16; i++) acc[i] = 0.f;

        const float* wp    = sw + oc * 27;
        const float* xbase = sx + (4 * ty) * P + 4 * tx;

        #pragma unroll
        for (int ci = 0; ci < 3; ci++) {
            const float* xp = xbase + ci * PH * P;
            float w0 = wp[0], w1 = wp[1], w2 = wp[2],
                  w3 = wp[3], w4 = wp[4], w5 = wp[5],
                  w6 = wp[6], w7 = wp[7], w8 = wp[8];
            wp += 9;
            float p[6][6];
            #pragma unroll
            for (int r = 0; r < 6; r++) {
                float4 a  = *reinterpret_cast<const float4*>(xp + r * P);
                float4 bq = *reinterpret_cast<const float4*>(xp + r * P + 4);
                p[r][0] = a.x;  p[r][1] = a.y;  p[r][2] = a.z;  p[r][3] = a.w;
                p[r][4] = bq.x; p[r][5] = bq.y;
            }
            #pragma unroll
            for (int r = 0; r < 4; r++) {
                #pragma unroll
                for (int c = 0; c < 4; c++) {
                    float s = acc[r * 4 + c];
                    s = fmaf(w0, p[r][c],         s);
                    s = fmaf(w1, p[r][c + 1],     s);
                    s = fmaf(w2, p[r][c + 2],     s);
                    s = fmaf(w3, p[r + 1][c],     s);
                    s = fmaf(w4, p[r + 1][c + 1], s);
                    s = fmaf(w5, p[r + 1][c + 2], s);
                    s = fmaf(w6, p[r + 2][c],     s);
                    s = fmaf(w7, p[r + 2][c + 1], s);
                    s = fmaf(w8, p[r + 2][c + 2], s);
                    acc[r * 4 + c] = s;
                }
            }
        }
        float bias = Bv[oc];
        size_t ob = (((size_t)b * OC + oc) * Sp + 2 * ty) * Sp + 2 * tx;
        #pragma unroll
        for (int pr = 0; pr < 2; pr++) {
            #pragma unroll
            for (int pc = 0; pc < 2; pc++) {
                float m = fmaxf(fmaxf(acc[(2*pr)*4 + 2*pc],   acc[(2*pr)*4 + 2*pc + 1]),
                                fmaxf(acc[(2*pr+1)*4 + 2*pc], acc[(2*pr+1)*4 + 2*pc + 1]));
                m += bias;
                if (branch) {   // private: leaky, fp32 out
                    float v = (m > 0.f) ? m : 0.001f * m;
                    p1[ob + pr * Sp + pc] = v;
                } else {        // shared: relu, packed out
                    float v = fmaxf(m, 0.f);
                    s1[ob + pr * Sp + pc] = pack_hilo(v);
                }
            }
        }
    }
}

// ---------------- merged FC: 256 blocks; first half fc2304(relu), second fc12288 -----
__global__ void fcmerged_kernel(const float* __restrict__ s3,  const float* __restrict__ WfW,
                                const float* __restrict__ Wfb,
                                const float* __restrict__ p1,  const float* __restrict__ PlW,
                                const float* __restrict__ Plb,
                                const int* __restrict__ dom_ptr,
                                float* __restrict__ out, int halfBlocks)
{
    const int warp = threadIdx.x >> 5;
    const int lane = threadIdx.x & 31;
    const bool priv = blockIdx.x >= halfBlocks;
    const int bb = (priv ? blockIdx.x - halfBlocks : blockIdx.x) * 8 + warp;

    int K, out_off;
    const float *X, *W, *Bv;
    bool relu;
    if (!priv) {
        K = 2304; X = s3; W = WfW; Bv = Wfb; relu = true; out_off = 0;
    } else {
        int dom = dom_ptr[0];
        K = 12288; X = p1; W = PlW + (size_t)dom * 12 * 12288;
        Bv = Plb + dom * 12; relu = false; out_off = 12;
    }
    const float4* xr = reinterpret_cast<const float4*>(X + (size_t)bb * K);

    float4 acc[12];
    #pragma unroll
    for (int j = 0; j < 12; j++) acc[j] = make_float4(0.f, 0.f, 0.f, 0.f);

    for (int k4 = lane; k4 < K / 4; k4 += 32) {
        float4 xv = xr[k4];
        #pragma unroll
        for (int j = 0; j < 12; j++) {
            float4 wv = reinterpret_cast<const float4*>(W + (size_t)j * K)[k4];
            acc[j].x = fmaf(xv.x, wv.x, acc[j].x);
            acc[j].y = fmaf(xv.y, wv.y, acc[j].y);
            acc[j].z = fmaf(xv.z, wv.z, acc[j].z);
            acc[j].w = fmaf(xv.w, wv.w, acc[j].w);
        }
    }
    #pragma unroll
    for (int j = 0; j < 12; j++) {
        float s = (acc[j].x + acc[j].y) + (acc[j].z + acc[j].w);
        #pragma unroll
        for (int o = 16; o > 0; o >>= 1) s += __shfl_xor_sync(0xffffffffu, s, o);
        if (lane == j) {
            float v = s + Bv[j];
            if (relu) v = fmaxf(v, 0.f);
            out[bb * 24 + out_off + j] = v;
        }
    }
}

// ---------------- per-sample routed heads: 24 -> 28 -> 14 -> 5 ----------------
__global__ void heads_kernel(const float* __restrict__ x24,
                             const int* __restrict__ tt,
                             const float* __restrict__ W1, const float* __restrict__ b1,
                             const float* __restrict__ W2, const float* __restrict__ b2,
                             const float* __restrict__ W3, const float* __restrict__ b3,
                             float* __restrict__ out)
{
    const int warp = threadIdx.x >> 5;
    const int lane = threadIdx.x & 31;
    const int b = blockIdx.x * 8 + warp;
    const int t = tt[b];

    float xv = (lane < 24) ? x24[b * 24 + lane] : 0.f;

    const float* w1 = W1 + t * 28 * 24 + min(lane, 27) * 24;
    float h1 = 0.f;
    #pragma unroll
    for (int k = 0; k < 24; k++)
        h1 = fmaf(w1[k], __shfl_sync(0xffffffffu, xv, k), h1);
    if (lane < 28) h1 += b1[t * 28 + lane];
    h1 = fmaxf(h1, 0.f);
    if (lane >= 28) h1 = 0.f;

    const float* w2 = W2 + t * 14 * 28 + min(lane, 13) * 28;
    float h2 = 0.f;
    #pragma unroll
    for (int k = 0; k < 28; k++)
        h2 = fmaf(w2[k], __shfl_sync(0xffffffffu, h1, k), h2);
    if (lane < 14) h2 += b2[t * 14 + lane];
    h2 = fmaxf(h2, 0.f);
    if (lane >= 14) h2 = 0.f;

    const float* w3 = W3 + t * 5 * 14 + min(lane, 4) * 14;
    float o = 0.f;
    #pragma unroll
    for (int k = 0; k < 14; k++)
        o = fmaf(w3[k], __shfl_sync(0xffffffffu, h2, k), o);
    if (lane < 5) out[b * 5 + lane] = o + b3[t * 5 + lane];
}

// ---------------- launch ----------------
extern "C" void kernel_launch(void* const* d_in, const int* in_sizes, int n_in,
                              void* d_out, int out_size)
{
    const float* x_s = (const float*)d_in[0];
    const float* x_p = (const float*)d_in[1];
    const int*   tt  = (const int*)d_in[2];
    const int*   dom = (const int*)d_in[3];
    const float* WsW = (const float*)d_in[4];
    const float* Wsb = (const float*)d_in[5];
    const float* WhW = (const float*)d_in[6];
    const float* Whb = (const float*)d_in[7];
    const float* WfW = (const float*)d_in[8];
    const float* Wfb = (const float*)d_in[9];
    const float* PcW = (const float*)d_in[10];
    const float* Pcb = (const float*)d_in[11];
    const float* PlW = (const float*)d_in[12];
    const float* Plb = (const float*)d_in[13];
    const float* H1W = (const float*)d_in[14];
    const float* H1b = (const float*)d_in[15];
    const float* H2W = (const float*)d_in[16];
    const float* H2b = (const float*)d_in[17];
    const float* H3W = (const float*)d_in[18];
    const float* H3b = (const float*)d_in[19];
    float* out = (float*)d_out;
    const int B = in_sizes[2];  // 1024

    unsigned *s1, *s2;
    float *s3, *p1, *x24, *Wf;
    cudaGetSymbolAddress((void**)&s1,  g_s1);
    cudaGetSymbolAddress((void**)&s2,  g_s2);
    cudaGetSymbolAddress((void**)&s3,  g_s3);
    cudaGetSymbolAddress((void**)&p1,  g_p1);
    cudaGetSymbolAddress((void**)&x24, g_x24);
    cudaGetSymbolAddress((void**)&Wf,  g_Wf);

    const size_t smc1 = (size_t)(3 * 66 * 68 + 36 * 27) * sizeof(float);       // 57.7 KB
    const size_t smb  = (size_t)(40 * 360 + 2 * 480 * 4) * sizeof(unsigned);   // 73.0 KB

    cudaFuncSetAttribute(c1p_kernel,
                         cudaFuncAttributeMaxDynamicSharedMemorySize, (int)smc1);
    cudaFuncSetAttribute(bfconv_kernel<32, 4, 36, 8, true>,
                         cudaFuncAttributeMaxDynamicSharedMemorySize, (int)smb);
    cudaFuncSetAttribute(bfconv_kernel<16, 1, 20, 8, false>,
                         cudaFuncAttributeMaxDynamicSharedMemorySize, (int)smb);

    // fragment-ready split weights, ord0 only (tiny; every launch, deterministic)
    wprep_kernel<<<(9 * 5 * 3 * 32 + 127) / 128, 128>>>(WhW, Wf);

    // conv1 + private conv in ONE launch (2048 blocks, better wave packing)
    c1p_kernel<<<dim3(B, 2), 256, smc1>>>(x_s, x_p, WsW, Wsb, PcW, Pcb, dom, s1, p1);
    // hidden convs (bf16-split MMA)
    bfconv_kernel<32, 4, 36, 8, true ><<<dim3(4, B), 256, smb>>>(s1, Wf, Whb, s2);
    bfconv_kernel<16, 1, 20, 8, false><<<dim3(1, B), 256, smb>>>(s2, Wf, Whb, s3);
    // both FCs in ONE launch -> concat buffer
    fcmerged_kernel<<<2 * (B / 8), 256>>>(s3, WfW, Wfb, p1, PlW, Plb, dom, x24, B / 8);
    // routed heads -> output
    heads_kernel<<<B / 8, 256>>>(x24, tt, H1W, H1b, H2W, H2b, H3W, H3b, out);
}

// round 16
// speedup vs baseline: 1.7701x; 1.0942x over previous
#include <cuda_runtime.h>
#include <cuda_bf16.h>
#include <cstdint>

// ---------------- scratch (device globals; no allocation allowed) ----------------
__device__ unsigned g_s1[1024 * 36 * 32 * 32]; // conv1 out, packed bf16x2(hi,lo)
__device__ unsigned g_s2[1024 * 36 * 16 * 16]; // conv2 out, packed bf16x2(hi,lo)
__device__ float    g_s3[1024 * 36 * 8 * 8];   // conv3 out (fp32, feeds FC)
__device__ float    g_p1[1024 * 12 * 32 * 32]; // private conv out
__device__ float    g_x24[1024 * 24];          // [12:24) = private fc out
__device__ float    g_Wf[9 * 5 * 3 * 32 * 4];  // hidden conv frag weights, ord0 (69 KB)

// ---------------- packing helpers ----------------
__device__ __forceinline__ unsigned pack_hilo(float v) {
    __nv_bfloat16 h = __float2bfloat16_rn(v);
    float hf = __bfloat162float(h);
    __nv_bfloat16 l = __float2bfloat16_rn(v - hf);
    return (((unsigned)__bfloat16_as_ushort(l)) << 16) | (unsigned)__bfloat16_as_ushort(h);
}
__device__ __forceinline__ unsigned rot16(unsigned w) {
    return (w << 16) | (w >> 16);
}
__device__ __forceinline__ void mma_bf16(float* d, const unsigned* a, unsigned b0, unsigned b1) {
    asm("mma.sync.aligned.m16n8k16.row.col.f32.bf16.bf16.f32 "
        "{%0,%1,%2,%3}, {%4,%5,%6,%7}, {%8,%9}, {%0,%1,%2,%3};"
        : "+f"(d[0]), "+f"(d[1]), "+f"(d[2]), "+f"(d[3])
        : "r"(a[0]), "r"(a[1]), "r"(a[2]), "r"(a[3]), "r"(b0), "r"(b1));
}

// ---------------- weight prep (hidden convs): ord0 only ----------------
__global__ void wprep_kernel(const float* __restrict__ W, float* __restrict__ Wf)
{
    int idx = blockIdx.x * blockDim.x + threadIdx.x;
    if (idx >= 9 * 5 * 3 * 32) return;
    int lane = idx & 31;
    int q    = (idx >> 5) % 3;
    int kt   = (idx / 96) % 5;
    int tap  = idx / 480;
    int km = lane & 3, n = lane >> 2;
    int ci0 = kt * 8 + km, ci1 = ci0 + 4;
    int oc0 = q * 16 + n,  oc1 = oc0 + 8;
    auto pk = [&](int ci, int oc) -> float {
        float w = 0.f;
        if (ci < 36 && oc < 36) w = W[((size_t)oc * 36 + ci) * 9 + tap];
        return __uint_as_float(pack_hilo(w));
    };
    float4 f;
    f.x = pk(ci0, oc0); f.y = pk(ci1, oc0);
    f.z = pk(ci0, oc1); f.w = pk(ci1, oc1);
    reinterpret_cast<float4*>(Wf)[idx] = f;
}

// ---------------- merged conv1 + private conv (fp32 direct, S=64, IC=3) --------------
__global__ void __launch_bounds__(256)
c1p_kernel(const float* __restrict__ x_s, const float* __restrict__ x_p,
           const float* __restrict__ WsW, const float* __restrict__ Wsb,
           const float* __restrict__ PcW, const float* __restrict__ Pcb,
           const int* __restrict__ dom_ptr,
           unsigned* __restrict__ s1, float* __restrict__ p1)
{
    constexpr int S = 64, PH = 66, P = 68, HT = 16, Sp = 32, NT = 256;
    extern __shared__ float smem[];
    float* sx = smem;
    float* sw = smem + 3 * PH * P;

    const int b      = blockIdx.x;
    const int branch = blockIdx.y;
    const int tid    = threadIdx.x;

    const int OC = branch ? 12 : 36;
    int dom = branch ? dom_ptr[0] : 0;
    const float* x  = branch ? x_p : x_s;
    const float* W  = branch ? (PcW + (size_t)dom * 12 * 27) : WsW;
    const float* Bv = branch ? (Pcb + dom * 12) : Wsb;

    for (int i = tid; i < 3 * PH * P; i += NT) sx[i] = 0.f;
    __syncthreads();
    const float* xb = x + (size_t)b * 3 * S * S;
    for (int i4 = tid; i4 < 3 * S * S / 4; i4 += NT) {
        int i = i4 * 4;
        int c  = i / (S * S);
        int r  = (i / S) % S;
        int cc = i % S;
        float4 v = *reinterpret_cast<const float4*>(xb + i);
        float* d = sx + c * PH * P + (r + 1) * P + cc + 1;
        d[0] = v.x; d[1] = v.y; d[2] = v.z; d[3] = v.w;
    }
    for (int i = tid; i < OC * 27; i += NT) sw[i] = W[i];
    __syncthreads();

    const int tiles = OC * HT * HT;
    for (int t = tid; t < tiles; t += NT) {
        int oc  = t >> 8;
        int rem = t & 255;
        int ty  = rem >> 4;
        int tx  = rem & 15;

        float acc[16];
        #pragma unroll
        for (int i = 0; i < 16; i++) acc[i] = 0.f;

        const float* wp    = sw + oc * 27;
        const float* xbase = sx + (4 * ty) * P + 4 * tx;

        #pragma unroll
        for (int ci = 0; ci < 3; ci++) {
            const float* xp = xbase + ci * PH * P;
            float w0 = wp[0], w1 = wp[1], w2 = wp[2],
                  w3 = wp[3], w4 = wp[4], w5 = wp[5],
                  w6 = wp[6], w7 = wp[7], w8 = wp[8];
            wp += 9;
            float p[6][6];
            #pragma unroll
            for (int r = 0; r < 6; r++) {
                float4 a  = *reinterpret_cast<const float4*>(xp + r * P);
                float4 bq = *reinterpret_cast<const float4*>(xp + r * P + 4);
                p[r][0] = a.x;  p[r][1] = a.y;  p[r][2] = a.z;  p[r][3] = a.w;
                p[r][4] = bq.x; p[r][5] = bq.y;
            }
            #pragma unroll
            for (int r = 0; r < 4; r++) {
                #pragma unroll
                for (int c = 0; c < 4; c++) {
                    float s = acc[r * 4 + c];
                    s = fmaf(w0, p[r][c],         s);
                    s = fmaf(w1, p[r][c + 1],     s);
                    s = fmaf(w2, p[r][c + 2],     s);
                    s = fmaf(w3, p[r + 1][c],     s);
                    s = fmaf(w4, p[r + 1][c + 1], s);
                    s = fmaf(w5, p[r + 1][c + 2], s);
                    s = fmaf(w6, p[r + 2][c],     s);
                    s = fmaf(w7, p[r + 2][c + 1], s);
                    s = fmaf(w8, p[r + 2][c + 2], s);
                    acc[r * 4 + c] = s;
                }
            }
        }
        float bias = Bv[oc];
        size_t ob = (((size_t)b * OC + oc) * Sp + 2 * ty) * Sp + 2 * tx;
        #pragma unroll
        for (int pr = 0; pr < 2; pr++) {
            #pragma unroll
            for (int pc = 0; pc < 2; pc++) {
                float m = fmaxf(fmaxf(acc[(2*pr)*4 + 2*pc],   acc[(2*pr)*4 + 2*pc + 1]),
                                fmaxf(acc[(2*pr+1)*4 + 2*pc], acc[(2*pr+1)*4 + 2*pc + 1]));
                m += bias;
                if (branch) {
                    float v = (m > 0.f) ? m : 0.001f * m;
                    p1[ob + pr * Sp + pc] = v;
                } else {
                    float v = fmaxf(m, 0.f);
                    s1[ob + pr * Sp + pc] = pack_hilo(v);
                }
            }
        }
    }
}

// ---------------- conv2 (bf16 MMA) + hidden fc_private rows ----------------
// grid = (5, B): strip<4 -> conv2 on strip; strip==4 -> fc_private for row b
// (8 warps split K=12288, smem cross-warp reduce). fc work rides in conv2's
// bubbles instead of a serial launch.
__global__ void __launch_bounds__(256)
conv2_fused_kernel(const unsigned* __restrict__ x, const float* __restrict__ Wf,
                   const float* __restrict__ Bv, unsigned* __restrict__ outp,
                   const float* __restrict__ p1, const float* __restrict__ PlW,
                   const float* __restrict__ Plb, const int* __restrict__ dom_ptr,
                   float* __restrict__ x24)
{
    constexpr int S = 32, STRIPS = 4, P = 36, NT = 256;
    constexpr int SR  = S / STRIPS;           // 8
    constexpr int PH  = SR + 2;               // 10
    constexpr int PHP = PH * P;               // 360
    static_assert(PHP % 32 == 8, "bank layout");
    constexpr int Sp = S / 2;
    constexpr int WTAP = 5 * 3 * 32;

    extern __shared__ unsigned sx[];
    const int strip = blockIdx.x;
    const int b     = blockIdx.y;
    const int tid   = threadIdx.x;
    const int w     = tid >> 5;
    const int lane  = tid & 31;

    if (strip == 4) {
        // ---- fc_private: one row (b), 8 warps split K=12288 ----
        float* sred = reinterpret_cast<float*>(sx);      // [8][12]
        int dom = dom_ptr[0];
        const float* W = PlW + (size_t)dom * 12 * 12288;
        const float4* xr = reinterpret_cast<const float4*>(p1 + (size_t)b * 12288);
        const int k0 = w * 384;                          // K4 = 3072, 384 per warp

        float4 acc[12];
        #pragma unroll
        for (int j = 0; j < 12; j++) acc[j] = make_float4(0.f, 0.f, 0.f, 0.f);
        for (int s = 0; s < 12; s++) {
            int k4 = k0 + s * 32 + lane;
            float4 xv = __ldg(xr + k4);
            #pragma unroll
            for (int j = 0; j < 12; j++) {
                float4 wv = __ldg(reinterpret_cast<const float4*>(W + (size_t)j * 12288) + k4);
                acc[j].x = fmaf(xv.x, wv.x, acc[j].x);
                acc[j].y = fmaf(xv.y, wv.y, acc[j].y);
                acc[j].z = fmaf(xv.z, wv.z, acc[j].z);
                acc[j].w = fmaf(xv.w, wv.w, acc[j].w);
            }
        }
        #pragma unroll
        for (int j = 0; j < 12; j++) {
            float s = (acc[j].x + acc[j].y) + (acc[j].z + acc[j].w);
            #pragma unroll
            for (int o = 16; o > 0; o >>= 1) s += __shfl_xor_sync(0xffffffffu, s, o);
            if (lane == j) sred[w * 12 + j] = s;
        }
        __syncthreads();
        if (w == 0 && lane < 12) {
            float s = 0.f;
            #pragma unroll
            for (int ww = 0; ww < 8; ww++) s += sred[ww * 12 + lane];
            x24[b * 24 + 12 + lane] = s + Plb[dom * 12 + lane];
        }
        return;
    }

    // ---- conv2 path (R15 bfconv, unchanged) ----
    float4* sB = reinterpret_cast<float4*>(sx + 40 * PHP);

    {
        uint4 z = make_uint4(0u, 0u, 0u, 0u);
        uint4* sz = reinterpret_cast<uint4*>(sx);
        for (int i = tid; i < 40 * PHP / 4; i += NT) sz[i] = z;
    }
    __syncthreads();

    const int r0  = strip * SR;
    const int gr0 = (r0 - 1 < 0) ? 0 : r0 - 1;
    const int gr1 = (r0 + SR + 1 > S) ? S : r0 + SR + 1;
    const int nrow = gr1 - gr0;
    const unsigned* xb = x + (size_t)b * 36 * S * S;
    for (int i4 = tid; i4 < 36 * nrow * S / 4; i4 += NT) {
        int i  = i4 * 4;
        int ci = i / (nrow * S);
        int rr = (i / S) % nrow;
        int c  = i % S;
        int gr = gr0 + rr;
        uint4 v = *reinterpret_cast<const uint4*>(xb + ci * S * S + gr * S + c);
        unsigned* d = sx + ci * PHP + (gr - r0 + 1) * P + c + 1;
        d[0] = v.x; d[1] = v.y; d[2] = v.z; d[3] = v.w;
    }
    const float4* Wf4 = reinterpret_cast<const float4*>(Wf);
    for (int i = tid; i < WTAP; i += NT) sB[i] = __ldg(Wf4 + i);
    __syncthreads();

    const int rp  = w >> 1;
    const int c0  = (w & 1) * 16;
    const int lr0 = 2 * rp;
    const int la  = lane & 3;
    const int lg  = lane >> 2;

    float C[5][2][4];
    #pragma unroll
    for (int n = 0; n < 5; n++)
        #pragma unroll
        for (int t = 0; t < 2; t++)
            #pragma unroll
            for (int j = 0; j < 4; j++) C[n][t][j] = 0.f;

    const int aoff0 = la * PHP + lr0 * P + c0 + lg;

    for (int tap = 0; tap < 9; tap++) {
        const int p = tap & 1;
        if (tap + 1 < 9) {
            const float4* src = Wf4 + (tap + 1) * WTAP;
            for (int i = tid; i < WTAP; i += NT) sB[(p ^ 1) * WTAP + i] = __ldg(src + i);
        }
        const int dy = tap / 3, dx = tap % 3;
        const int abase = aoff0 + dy * P + dx;
        const float4* bt = sB + p * WTAP;

        #pragma unroll
        for (int kt = 0; kt < 5; kt++) {
            unsigned A[2][4];
            #pragma unroll
            for (int t = 0; t < 2; t++) {
                const unsigned* ap = sx + abase + t * P + kt * 8 * PHP;
                A[t][0] = ap[0];
                A[t][1] = ap[8];
                A[t][2] = ap[4 * PHP];
                A[t][3] = ap[4 * PHP + 8];
            }
            float4 q0 = bt[kt * 96 + 0 * 32 + lane];
            float4 q1 = bt[kt * 96 + 1 * 32 + lane];
            float4 q2 = bt[kt * 96 + 2 * 32 + lane];

            unsigned Bw[5][2] = {
                {__float_as_uint(q0.x), __float_as_uint(q0.y)},
                {__float_as_uint(q0.z), __float_as_uint(q0.w)},
                {__float_as_uint(q1.x), __float_as_uint(q1.y)},
                {__float_as_uint(q1.z), __float_as_uint(q1.w)},
                {__float_as_uint(q2.x), __float_as_uint(q2.y)} };
            unsigned Br[5][2];
            #pragma unroll
            for (int n = 0; n < 5; n++) {
                Br[n][0] = rot16(Bw[n][0]);
                Br[n][1] = rot16(Bw[n][1]);
            }
            #pragma unroll
            for (int n = 0; n < 5; n++)
                #pragma unroll
                for (int t = 0; t < 2; t++)
                    mma_bf16(C[n][t], A[t], Bw[n][0], Bw[n][1]);
            #pragma unroll
            for (int n = 0; n < 5; n++)
                #pragma unroll
                for (int t = 0; t < 2; t++)
                    mma_bf16(C[n][t], A[t], Br[n][0], Br[n][1]);
        }
        __syncthreads();
    }

    const int pr = strip * (SR / 2) + rp;
    #pragma unroll
    for (int n = 0; n < 5; n++) {
        float m0 = fmaxf(C[n][0][0], C[n][1][0]);
        float m1 = fmaxf(C[n][0][1], C[n][1][1]);
        float m2 = fmaxf(C[n][0][2], C[n][1][2]);
        float m3 = fmaxf(C[n][0][3], C[n][1][3]);
        float p0 = fmaxf(m0, __shfl_xor_sync(0xffffffffu, m0, 4));
        float p1v = fmaxf(m1, __shfl_xor_sync(0xffffffffu, m1, 4));
        float p2 = fmaxf(m2, __shfl_xor_sync(0xffffffffu, m2, 4));
        float p3 = fmaxf(m3, __shfl_xor_sync(0xffffffffu, m3, 4));
        if ((lane & 4) == 0) {
            int oc0 = n * 8 + (lane & 3) * 2;
            if (oc0 < 36) {
                int pcb = c0 / 2 + ((lane >> 3) & 3);
                float b0 = __ldg(Bv + oc0);
                float b1 = __ldg(Bv + oc0 + 1);
                size_t o0 = (((size_t)b * 36 + oc0) * Sp + pr) * Sp;
                size_t o1 = o0 + (size_t)Sp * Sp;
                outp[o0 + pcb]     = pack_hilo(fmaxf(p0  + b0, 0.f));
                outp[o1 + pcb]     = pack_hilo(fmaxf(p1v + b1, 0.f));
                outp[o0 + pcb + 4] = pack_hilo(fmaxf(p2  + b0, 0.f));
                outp[o1 + pcb + 4] = pack_hilo(fmaxf(p3  + b1, 0.f));
            }
        }
    }
}

// ---------------- conv3 (bf16 MMA, R15 unchanged) ----------------
template <int S, int STRIPS, int P, int NWARPS, bool OUTPACK>
__global__ void __launch_bounds__(NWARPS * 32)
bfconv_kernel(const unsigned* __restrict__ x, const float* __restrict__ Wf,
              const float* __restrict__ Bv, void* __restrict__ outv)
{
    constexpr int NT  = NWARPS * 32;
    constexpr int SR  = S / STRIPS;
    constexpr int PH  = SR + 2;
    constexpr int PHP = PH * P;
    static_assert(PHP % 32 == 8, "bank layout");
    constexpr int RPAIRS = SR / 2;
    constexpr int COLT   = S / 16;
    static_assert(RPAIRS * COLT == NWARPS, "warp count");
    constexpr int Sp = S / 2;
    constexpr int WTAP = 5 * 3 * 32;

    extern __shared__ unsigned sx[];
    float4* sB = reinterpret_cast<float4*>(sx + 40 * PHP);

    const int strip = blockIdx.x;
    const int b     = blockIdx.y;
    const int tid   = threadIdx.x;
    const int w     = tid >> 5;
    const int lane  = tid & 31;

    {
        uint4 z = make_uint4(0u, 0u, 0u, 0u);
        uint4* sz = reinterpret_cast<uint4*>(sx);
        for (int i = tid; i < 40 * PHP / 4; i += NT) sz[i] = z;
    }
    __syncthreads();

    const int r0  = strip * SR;
    const int gr0 = (r0 - 1 < 0) ? 0 : r0 - 1;
    const int gr1 = (r0 + SR + 1 > S) ? S : r0 + SR + 1;
    const int nrow = gr1 - gr0;
    const unsigned* xb = x + (size_t)b * 36 * S * S;
    for (int i4 = tid; i4 < 36 * nrow * S / 4; i4 += NT) {
        int i  = i4 * 4;
        int ci = i / (nrow * S);
        int rr = (i / S) % nrow;
        int c  = i % S;
        int gr = gr0 + rr;
        uint4 v = *reinterpret_cast<const uint4*>(xb + ci * S * S + gr * S + c);
        unsigned* d = sx + ci * PHP + (gr - r0 + 1) * P + c + 1;
        d[0] = v.x; d[1] = v.y; d[2] = v.z; d[3] = v.w;
    }
    const float4* Wf4 = reinterpret_cast<const float4*>(Wf);
    for (int i = tid; i < WTAP; i += NT) sB[i] = __ldg(Wf4 + i);
    __syncthreads();

    const int rp  = w / COLT;
    const int c0  = (w % COLT) * 16;
    const int lr0 = 2 * rp;
    const int la  = lane & 3;
    const int lg  = lane >> 2;

    float C[5][2][4];
    #pragma unroll
    for (int n = 0; n < 5; n++)
        #pragma unroll
        for (int t = 0; t < 2; t++)
            #pragma unroll
            for (int j = 0; j < 4; j++) C[n][t][j] = 0.f;

    const int aoff0 = la * PHP + lr0 * P + c0 + lg;

    for (int tap = 0; tap < 9; tap++) {
        const int p = tap & 1;
        if (tap + 1 < 9) {
            const float4* src = Wf4 + (tap + 1) * WTAP;
            for (int i = tid; i < WTAP; i += NT) sB[(p ^ 1) * WTAP + i] = __ldg(src + i);
        }
        const int dy = tap / 3, dx = tap % 3;
        const int abase = aoff0 + dy * P + dx;
        const float4* bt = sB + p * WTAP;

        #pragma unroll
        for (int kt = 0; kt < 5; kt++) {
            unsigned A[2][4];
            #pragma unroll
            for (int t = 0; t < 2; t++) {
                const unsigned* ap = sx + abase + t * P + kt * 8 * PHP;
                A[t][0] = ap[0];
                A[t][1] = ap[8];
                A[t][2] = ap[4 * PHP];
                A[t][3] = ap[4 * PHP + 8];
            }
            float4 q0 = bt[kt * 96 + 0 * 32 + lane];
            float4 q1 = bt[kt * 96 + 1 * 32 + lane];
            float4 q2 = bt[kt * 96 + 2 * 32 + lane];

            unsigned Bw[5][2] = {
                {__float_as_uint(q0.x), __float_as_uint(q0.y)},
                {__float_as_uint(q0.z), __float_as_uint(q0.w)},
                {__float_as_uint(q1.x), __float_as_uint(q1.y)},
                {__float_as_uint(q1.z), __float_as_uint(q1.w)},
                {__float_as_uint(q2.x), __float_as_uint(q2.y)} };
            unsigned Br[5][2];
            #pragma unroll
            for (int n = 0; n < 5; n++) {
                Br[n][0] = rot16(Bw[n][0]);
                Br[n][1] = rot16(Bw[n][1]);
            }
            #pragma unroll
            for (int n = 0; n < 5; n++)
                #pragma unroll
                for (int t = 0; t < 2; t++)
                    mma_bf16(C[n][t], A[t], Bw[n][0], Bw[n][1]);
            #pragma unroll
            for (int n = 0; n < 5; n++)
                #pragma unroll
                for (int t = 0; t < 2; t++)
                    mma_bf16(C[n][t], A[t], Br[n][0], Br[n][1]);
        }
        __syncthreads();
    }

    const int pr = strip * RPAIRS + rp;
    #pragma unroll
    for (int n = 0; n < 5; n++) {
        float m0 = fmaxf(C[n][0][0], C[n][1][0]);
        float m1 = fmaxf(C[n][0][1], C[n][1][1]);
        float m2 = fmaxf(C[n][0][2], C[n][1][2]);
        float m3 = fmaxf(C[n][0][3], C[n][1][3]);
        float p0 = fmaxf(m0, __shfl_xor_sync(0xffffffffu, m0, 4));
        float p1 = fmaxf(m1, __shfl_xor_sync(0xffffffffu, m1, 4));
        float p2 = fmaxf(m2, __shfl_xor_sync(0xffffffffu, m2, 4));
        float p3 = fmaxf(m3, __shfl_xor_sync(0xffffffffu, m3, 4));
        if ((lane & 4) == 0) {
            int oc0 = n * 8 + (lane & 3) * 2;
            if (oc0 < 36) {
                int pcb = c0 / 2 + ((lane >> 3) & 3);
                float b0 = __ldg(Bv + oc0);
                float b1 = __ldg(Bv + oc0 + 1);
                float v00 = fmaxf(p0 + b0, 0.f);
                float v01 = fmaxf(p1 + b1, 0.f);
                float v10 = fmaxf(p2 + b0, 0.f);
                float v11 = fmaxf(p3 + b1, 0.f);
                size_t o0 = (((size_t)b * 36 + oc0) * Sp + pr) * Sp;
                size_t o1 = o0 + (size_t)Sp * Sp;
                if (OUTPACK) {
                    unsigned* out = (unsigned*)outv;
                    out[o0 + pcb]     = pack_hilo(v00);
                    out[o1 + pcb]     = pack_hilo(v01);
                    out[o0 + pcb + 4] = pack_hilo(v10);
                    out[o1 + pcb + 4] = pack_hilo(v11);
                } else {
                    float* out = (float*)outv;
                    out[o0 + pcb]     = v00;
                    out[o1 + pcb]     = v01;
                    out[o0 + pcb + 4] = v10;
                    out[o1 + pcb + 4] = v11;
                }
            }
        }
    }
}

// ---------------- fc_shared (2304, relu) fused with routed heads ----------------
// Warp = one sample row: compute h (lanes 0-11 in-register), read private half
// from x24[12:24), then run the shuffle-GEMV heads directly. One launch, no
// intermediate h round-trip.
__global__ void fcheads_kernel(const float* __restrict__ s3,
                               const float* __restrict__ WfW, const float* __restrict__ Wfb,
                               const float* __restrict__ x24,
                               const int* __restrict__ tt,
                               const float* __restrict__ W1, const float* __restrict__ b1,
                               const float* __restrict__ W2, const float* __restrict__ b2,
                               const float* __restrict__ W3, const float* __restrict__ b3,
                               float* __restrict__ out)
{
    const int warp = threadIdx.x >> 5;
    const int lane = threadIdx.x & 31;
    const int b = blockIdx.x * 8 + warp;

    const float4* xr = reinterpret_cast<const float4*>(s3 + (size_t)b * 2304);
    float4 acc[12];
    #pragma unroll
    for (int j = 0; j < 12; j++) acc[j] = make_float4(0.f, 0.f, 0.f, 0.f);
    for (int k4 = lane; k4 < 576; k4 += 32) {
        float4 xv = xr[k4];
        #pragma unroll
        for (int j = 0; j < 12; j++) {
            float4 wv = reinterpret_cast<const float4*>(WfW + (size_t)j * 2304)[k4];
            acc[j].x = fmaf(xv.x, wv.x, acc[j].x);
            acc[j].y = fmaf(xv.y, wv.y, acc[j].y);
            acc[j].z = fmaf(xv.z, wv.z, acc[j].z);
            acc[j].w = fmaf(xv.w, wv.w, acc[j].w);
        }
    }
    float xv = 0.f;
    #pragma unroll
    for (int j = 0; j < 12; j++) {
        float s = (acc[j].x + acc[j].y) + (acc[j].z + acc[j].w);
        #pragma unroll
        for (int o = 16; o > 0; o >>= 1) s += __shfl_xor_sync(0xffffffffu, s, o);
        if (lane == j) xv = fmaxf(s + Wfb[j], 0.f);    // shared h in lanes 0-11
    }
    if (lane >= 12 && lane < 24) xv = x24[b * 24 + lane];   // private half

    // ---- routed heads (validated shuffle GEMV chain) ----
    const int t = tt[b];
    const float* w1 = W1 + t * 28 * 24 + min(lane, 27) * 24;
    float h1 = 0.f;
    #pragma unroll
    for (int k = 0; k < 24; k++)
        h1 = fmaf(w1[k], __shfl_sync(0xffffffffu, xv, k), h1);
    if (lane < 28) h1 += b1[t * 28 + lane];
    h1 = fmaxf(h1, 0.f);
    if (lane >= 28) h1 = 0.f;

    const float* w2 = W2 + t * 14 * 28 + min(lane, 13) * 28;
    float h2 = 0.f;
    #pragma unroll
    for (int k = 0; k < 28; k++)
        h2 = fmaf(w2[k], __shfl_sync(0xffffffffu, h1, k), h2);
    if (lane < 14) h2 += b2[t * 14 + lane];
    h2 = fmaxf(h2, 0.f);
    if (lane >= 14) h2 = 0.f;

    const float* w3 = W3 + t * 5 * 14 + min(lane, 4) * 14;
    float o = 0.f;
    #pragma unroll
    for (int k = 0; k < 14; k++)
        o = fmaf(w3[k], __shfl_sync(0xffffffffu, h2, k), o);
    if (lane < 5) out[b * 5 + lane] = o + b3[t * 5 + lane];
}

// ---------------- launch ----------------
extern "C" void kernel_launch(void* const* d_in, const int* in_sizes, int n_in,
                              void* d_out, int out_size)
{
    const float* x_s = (const float*)d_in[0];
    const float* x_p = (const float*)d_in[1];
    const int*   tt  = (const int*)d_in[2];
    const int*   dom = (const int*)d_in[3];
    const float* WsW = (const float*)d_in[4];
    const float* Wsb = (const float*)d_in[5];
    const float* WhW = (const float*)d_in[6];
    const float* Whb = (const float*)d_in[7];
    const float* WfW = (const float*)d_in[8];
    const float* Wfb = (const float*)d_in[9];
    const float* PcW = (const float*)d_in[10];
    const float* Pcb = (const float*)d_in[11];
    const float* PlW = (const float*)d_in[12];
    const float* Plb = (const float*)d_in[13];
    const float* H1W = (const float*)d_in[14];
    const float* H1b = (const float*)d_in[15];
    const float* H2W = (const float*)d_in[16];
    const float* H2b = (const float*)d_in[17];
    const float* H3W = (const float*)d_in[18];
    const float* H3b = (const float*)d_in[19];
    float* out = (float*)d_out;
    const int B = in_sizes[2];  // 1024

    unsigned *s1, *s2;
    float *s3, *p1, *x24, *Wf;
    cudaGetSymbolAddress((void**)&s1,  g_s1);
    cudaGetSymbolAddress((void**)&s2,  g_s2);
    cudaGetSymbolAddress((void**)&s3,  g_s3);
    cudaGetSymbolAddress((void**)&p1,  g_p1);
    cudaGetSymbolAddress((void**)&x24, g_x24);
    cudaGetSymbolAddress((void**)&Wf,  g_Wf);

    const size_t smc1 = (size_t)(3 * 66 * 68 + 36 * 27) * sizeof(float);       // 57.7 KB
    const size_t smb  = (size_t)(40 * 360 + 2 * 480 * 4) * sizeof(unsigned);   // 73.0 KB

    cudaFuncSetAttribute(c1p_kernel,
                         cudaFuncAttributeMaxDynamicSharedMemorySize, (int)smc1);
    cudaFuncSetAttribute(conv2_fused_kernel,
                         cudaFuncAttributeMaxDynamicSharedMemorySize, (int)smb);
    cudaFuncSetAttribute(bfconv_kernel<16, 1, 20, 8, false>,
                         cudaFuncAttributeMaxDynamicSharedMemorySize, (int)smb);

    // fragment-ready split weights
    wprep_kernel<<<(9 * 5 * 3 * 32 + 127) / 128, 128>>>(WhW, Wf);
    // conv1 + private conv in one launch
    c1p_kernel<<<dim3(B, 2), 256, smc1>>>(x_s, x_p, WsW, Wsb, PcW, Pcb, dom, s1, p1);
    // conv2 with fc_private hidden in its grid
    conv2_fused_kernel<<<dim3(5, B), 256, smb>>>(s1, Wf, Whb, s2, p1, PlW, Plb, dom, x24);
    // conv3
    bfconv_kernel<16, 1, 20, 8, false><<<dim3(1, B), 256, smb>>>(s2, Wf, Whb, s3);
    // fc_shared fused with routed heads -> output
    fcheads_kernel<<<B / 8, 256>>>(s3, WfW, Wfb, x24, tt,
                                   H1W, H1b, H2W, H2b, H3W, H3b, out);
}